// round 9
// baseline (speedup 1.0000x reference)
#include <cuda_runtime.h>
#include <cuda_bf16.h>
#include <stdint.h>
#include <math.h>

typedef unsigned int u32;

#define NN 50000
#define EMAX 600000
#define ETOT_MAX (EMAX + NN)
#define NBLK ((NN + 1023) / 1024)   // 49
#define GEMM_TILES ((NN + 127) / 128)  // 391
#define GEMM_GRID 296                  // 148 SMs x occupancy 2

// ---------------- scratch (device globals; no allocations allowed) ----------
__device__ float g_hp[(size_t)NN * 128];
__device__ float g_actA[(size_t)NN * 128];
__device__ float g_actB[(size_t)NN * 128];
__device__ float g_hp2[NN * 10];
__device__ float g_as[NN * 4];
__device__ float g_ad[NN * 4];
__device__ float g_as2[NN];
__device__ float g_ad2[NN];
__device__ int   g_deg[NN];
__device__ int   g_off[NN + 1];
__device__ int   g_cur[NN];
__device__ int   g_csr[ETOT_MAX];
__device__ int   g_bsum[NBLK];
__device__ int   g_is64;

// host-side stream/event resources, created once at program init.
struct HxStreams {
    cudaStream_t s2;
    cudaEvent_t fork, join;
    HxStreams() {
        cudaStreamCreateWithFlags(&s2, cudaStreamNonBlocking);
        cudaEventCreateWithFlags(&fork, cudaEventDisableTiming);
        cudaEventCreateWithFlags(&join, cudaEventDisableTiming);
    }
};
static HxStreams g_hx;

// ---------------- edge-index dtype probe --------------------------------------
__global__ void k_probe(const int* __restrict__ ei32) {
    if (threadIdx.x == 0) {
        int ok = 1;
        for (int e = 0; e < 64; e++)
            if (ei32[2 * e + 1] != 0) { ok = 0; break; }
        g_is64 = ok;
    }
}

__device__ __forceinline__ int load_idx(const void* ei, long long pos) {
    if (g_is64) return (int)((const long long*)ei)[pos];
    return ((const int*)ei)[pos];
}

// ---------------- CSR build --------------------------------------------------
__global__ void k_hist(const void* __restrict__ ei, int E, int Etot) {
    int e = blockIdx.x * blockDim.x + threadIdx.x;
    if (e >= Etot) return;
    int d = (e < E) ? load_idx(ei, (long long)E + e) : (e - E);
    atomicAdd(&g_deg[d], 1);
}

__global__ void k_scan_a() {
    __shared__ int sh[1024];
    int b = blockIdx.x, t = threadIdx.x;
    int i = b * 1024 + t;
    int v = (i < NN) ? g_deg[i] : 0;
    sh[t] = v;
    __syncthreads();
    for (int off = 1; off < 1024; off <<= 1) {
        int u = (t >= off) ? sh[t - off] : 0;
        __syncthreads();
        sh[t] += u;
        __syncthreads();
    }
    if (i < NN) g_off[i] = sh[t] - v;
    if (t == 1023) g_bsum[b] = sh[t];
}

__global__ void k_scan_c() {
    __shared__ int pre[NBLK];
    if (threadIdx.x == 0) {
        int run = 0;
        for (int b = 0; b < NBLK; b++) { pre[b] = run; run += g_bsum[b]; }
        if (blockIdx.x == 0) g_off[NN] = run;
    }
    __syncthreads();
    int i = blockIdx.x * blockDim.x + threadIdx.x;
    if (i >= NN) return;
    int o = g_off[i] + pre[i >> 10];
    g_off[i] = o;
    g_cur[i] = o;
}

__global__ void k_scatter(const void* __restrict__ ei, int E, int Etot) {
    int e = blockIdx.x * blockDim.x + threadIdx.x;
    if (e >= Etot) return;
    int s, d;
    if (e < E) {
        s = load_idx(ei, e);
        d = load_idx(ei, (long long)E + e);
    } else {
        s = d = e - E;
    }
    int pos = atomicAdd(&g_cur[d], 1);
    g_csr[pos] = s;
}

// ---------------- tensor-core GEMM helpers -----------------------------------
__device__ __forceinline__ u32 s2u(const void* p) {
    return (u32)__cvta_generic_to_shared(p);
}
__device__ __forceinline__ void ldsm4(u32& r0, u32& r1, u32& r2, u32& r3, u32 addr) {
    asm volatile("ldmatrix.sync.aligned.m8n8.x4.shared.b16 {%0,%1,%2,%3}, [%4];"
                 : "=r"(r0), "=r"(r1), "=r"(r2), "=r"(r3) : "r"(addr));
}
__device__ __forceinline__ void ldsm4t(u32& r0, u32& r1, u32& r2, u32& r3, u32 addr) {
    asm volatile("ldmatrix.sync.aligned.m8n8.x4.trans.shared.b16 {%0,%1,%2,%3}, [%4];"
                 : "=r"(r0), "=r"(r1), "=r"(r2), "=r"(r3) : "r"(addr));
}
__device__ __forceinline__ void mma16816(float* c, const u32* a, u32 b0, u32 b1) {
    asm volatile(
        "mma.sync.aligned.m16n8k16.row.col.f32.bf16.bf16.f32 "
        "{%0,%1,%2,%3}, {%4,%5,%6,%7}, {%8,%9}, {%0,%1,%2,%3};"
        : "+f"(c[0]), "+f"(c[1]), "+f"(c[2]), "+f"(c[3])
        : "r"(a[0]), "r"(a[1]), "r"(a[2]), "r"(a[3]), "r"(b0), "r"(b1));
}
__device__ __forceinline__ void split4(float4 v, __nv_bfloat16* ph, __nv_bfloat16* pl) {
    __nv_bfloat16 h0 = __float2bfloat16(v.x);
    __nv_bfloat16 h1 = __float2bfloat16(v.y);
    __nv_bfloat16 h2 = __float2bfloat16(v.z);
    __nv_bfloat16 h3 = __float2bfloat16(v.w);
    ph[0] = h0; ph[1] = h1; ph[2] = h2; ph[3] = h3;
    pl[0] = __float2bfloat16(v.x - __bfloat162float(h0));
    pl[1] = __float2bfloat16(v.y - __bfloat162float(h1));
    pl[2] = __float2bfloat16(v.z - __bfloat162float(h2));
    pl[3] = __float2bfloat16(v.w - __bfloat162float(h3));
}

// C[n,128] = A[n,128] @ W[128,128] via bf16x2 split mma + fused attn dots.
// PERSISTENT: GEMM_GRID blocks grid-stride over row tiles (no wave quantization).
#define APAD 40
#define WPAD 136
__global__ void __launch_bounds__(256, 2)
k_gemm128(const float* __restrict__ A, const float* __restrict__ W,
          const float* __restrict__ att_s, const float* __restrict__ att_d,
          float* __restrict__ C, int n) {
    __shared__ __align__(16) __nv_bfloat16 Ah[128][APAD];
    __shared__ __align__(16) __nv_bfloat16 Al[128][APAD];
    __shared__ __align__(16) __nv_bfloat16 Wh[32][WPAD];
    __shared__ __align__(16) __nv_bfloat16 Wl[32][WPAD];

    int tid = threadIdx.x;
    int lane = tid & 31;
    int wid = tid >> 5;
    int warp_m = wid >> 1;
    int warp_n = wid & 1;
    int wrow0 = warp_m * 32;
    int wcol0 = warp_n * 64;

    int a_r = tid >> 3;
    int a_c = (tid & 7) * 4;
    int w_k = tid >> 3;

    // attn vectors are tile-invariant
    float2 vs[8], vd[8];
#pragma unroll
    for (int j = 0; j < 8; j++) {
        int col = wcol0 + j * 8 + (lane & 3) * 2;
        vs[j] = *(const float2*)(att_s + col);
        vd[j] = *(const float2*)(att_d + col);
    }

    int ntiles = (n + 127) >> 7;
    for (int tile = blockIdx.x; tile < ntiles; tile += gridDim.x) {
        int row0 = tile << 7;

        float acc[2][8][4];
#pragma unroll
        for (int i = 0; i < 2; i++)
#pragma unroll
            for (int j = 0; j < 8; j++)
#pragma unroll
                for (int q = 0; q < 4; q++) acc[i][j][q] = 0.f;

        float4 pa[4], pw[4];
#pragma unroll
        for (int it = 0; it < 4; it++) {
            int grow = row0 + a_r + it * 32;
            pa[it] = make_float4(0.f, 0.f, 0.f, 0.f);
            if (grow < n) pa[it] = *(const float4*)(A + (size_t)grow * 128 + a_c);
            pw[it] = *(const float4*)(W + (size_t)w_k * 128 + (tid & 7) * 4 + it * 32);
        }

        for (int k0 = 0; k0 < 128; k0 += 32) {
#pragma unroll
            for (int it = 0; it < 4; it++) {
                int r = a_r + it * 32;
                split4(pa[it], &Ah[r][a_c], &Al[r][a_c]);
                int c = (tid & 7) * 4 + it * 32;
                split4(pw[it], &Wh[w_k][c], &Wl[w_k][c]);
            }
            __syncthreads();

            if (k0 + 32 < 128) {
#pragma unroll
                for (int it = 0; it < 4; it++) {
                    int grow = row0 + a_r + it * 32;
                    pa[it] = make_float4(0.f, 0.f, 0.f, 0.f);
                    if (grow < n) pa[it] = *(const float4*)(A + (size_t)grow * 128 + k0 + 32 + a_c);
                    pw[it] = *(const float4*)(W + (size_t)(k0 + 32 + w_k) * 128 + (tid & 7) * 4 + it * 32);
                }
            }

#pragma unroll
            for (int ks = 0; ks < 32; ks += 16) {
                u32 ah[2][4], al[2][4], bb[4][4];
                int arow = (lane & 15);
                int acol = ks + ((lane >> 4) << 3);
#pragma unroll
                for (int mt = 0; mt < 2; mt++)
                    ldsm4(ah[mt][0], ah[mt][1], ah[mt][2], ah[mt][3],
                          s2u(&Ah[wrow0 + mt * 16 + arow][acol]));
#pragma unroll
                for (int p = 0; p < 4; p++) {
                    int j = p * 2 + (lane >> 4);
                    ldsm4t(bb[p][0], bb[p][1], bb[p][2], bb[p][3],
                           s2u(&Wh[ks + (lane & 15)][wcol0 + j * 8]));
                }
#pragma unroll
                for (int mt = 0; mt < 2; mt++)
#pragma unroll
                    for (int j = 0; j < 8; j++)
                        mma16816(acc[mt][j], ah[mt], bb[j >> 1][(j & 1) * 2], bb[j >> 1][(j & 1) * 2 + 1]);
#pragma unroll
                for (int mt = 0; mt < 2; mt++)
                    ldsm4(al[mt][0], al[mt][1], al[mt][2], al[mt][3],
                          s2u(&Al[wrow0 + mt * 16 + arow][acol]));
#pragma unroll
                for (int mt = 0; mt < 2; mt++)
#pragma unroll
                    for (int j = 0; j < 8; j++)
                        mma16816(acc[mt][j], al[mt], bb[j >> 1][(j & 1) * 2], bb[j >> 1][(j & 1) * 2 + 1]);
#pragma unroll
                for (int p = 0; p < 4; p++) {
                    int j = p * 2 + (lane >> 4);
                    ldsm4t(bb[p][0], bb[p][1], bb[p][2], bb[p][3],
                           s2u(&Wl[ks + (lane & 15)][wcol0 + j * 8]));
                }
#pragma unroll
                for (int mt = 0; mt < 2; mt++)
#pragma unroll
                    for (int j = 0; j < 8; j++)
                        mma16816(acc[mt][j], ah[mt], bb[j >> 1][(j & 1) * 2], bb[j >> 1][(j & 1) * 2 + 1]);
            }
            __syncthreads();
        }

        // epilogue: store C + fused attention dots
#pragma unroll
        for (int mt = 0; mt < 2; mt++) {
            int r0 = row0 + wrow0 + mt * 16 + (lane >> 2);
            int r1 = r0 + 8;
            float ps0[2] = {0.f, 0.f}, ps1[2] = {0.f, 0.f};
            float pd0[2] = {0.f, 0.f}, pd1[2] = {0.f, 0.f};
#pragma unroll
            for (int j = 0; j < 8; j++) {
                int cofs = wcol0 + j * 8 + (lane & 3) * 2;
                if (r0 < n)
                    *(float2*)(C + (size_t)r0 * 128 + cofs) = make_float2(acc[mt][j][0], acc[mt][j][1]);
                if (r1 < n)
                    *(float2*)(C + (size_t)r1 * 128 + cofs) = make_float2(acc[mt][j][2], acc[mt][j][3]);
                int h = j >> 2;
                ps0[h] += acc[mt][j][0] * vs[j].x + acc[mt][j][1] * vs[j].y;
                ps1[h] += acc[mt][j][2] * vs[j].x + acc[mt][j][3] * vs[j].y;
                pd0[h] += acc[mt][j][0] * vd[j].x + acc[mt][j][1] * vd[j].y;
                pd1[h] += acc[mt][j][2] * vd[j].x + acc[mt][j][3] * vd[j].y;
            }
#pragma unroll
            for (int o = 1; o <= 2; o <<= 1) {
#pragma unroll
                for (int h = 0; h < 2; h++) {
                    ps0[h] += __shfl_xor_sync(0xffffffffu, ps0[h], o);
                    ps1[h] += __shfl_xor_sync(0xffffffffu, ps1[h], o);
                    pd0[h] += __shfl_xor_sync(0xffffffffu, pd0[h], o);
                    pd1[h] += __shfl_xor_sync(0xffffffffu, pd1[h], o);
                }
            }
            if ((lane & 3) == 0) {
#pragma unroll
                for (int h = 0; h < 2; h++) {
                    int hd = warp_n * 2 + h;
                    if (r0 < n) { g_as[r0 * 4 + hd] = ps0[h]; g_ad[r0 * 4 + hd] = pd0[h]; }
                    if (r1 < n) { g_as[r1 * 4 + hd] = ps1[h]; g_ad[r1 * 4 + hd] = pd1[h]; }
                }
            }
        }
    }
}

__device__ __forceinline__ float leaky(float x) { return x > 0.f ? x : 0.2f * x; }

// ---------------- single-pass segment softmax + aggregate + bias/BN/ELU ------
#define CHUNK 64
__global__ void k_aggregate128(const float* __restrict__ bias, const float* __restrict__ gamma,
                               const float* __restrict__ beta, float* __restrict__ out, int n) {
    __shared__ float4 s_wv[8][CHUNK];
    __shared__ int    s_idx[8][CHUNK];
    int gt = blockIdx.x * blockDim.x + threadIdx.x;
    int node = gt >> 5;
    if (node >= n) return;
    int lane = threadIdx.x & 31;
    int wrp = (threadIdx.x >> 5);
    int s0 = g_off[node], s1 = g_off[node + 1];

    float ad0 = g_ad[node * 4 + 0], ad1 = g_ad[node * 4 + 1];
    float ad2 = g_ad[node * 4 + 2], ad3 = g_ad[node * 4 + 3];

    int hl = lane >> 3;
    float dl0 = 0.f, dl1 = 0.f, dl2 = 0.f, dl3 = 0.f;
    float ax = 0.f, ay = 0.f, az = 0.f, aw = 0.f;

    for (int c0 = s0; c0 < s1; c0 += CHUNK) {
        int cnt = min(CHUNK, s1 - c0);
        for (int i = lane; i < cnt; i += 32) {
            int s = g_csr[c0 + i];
            float4 av = *(const float4*)(g_as + s * 4);
            float4 wv;
            wv.x = __expf(leaky(av.x + ad0));
            wv.y = __expf(leaky(av.y + ad1));
            wv.z = __expf(leaky(av.z + ad2));
            wv.w = __expf(leaky(av.w + ad3));
            dl0 += wv.x; dl1 += wv.y; dl2 += wv.z; dl3 += wv.w;
            s_wv[wrp][i] = wv;
            s_idx[wrp][i] = s;
        }
        __syncwarp();
#pragma unroll 4
        for (int j = 0; j < cnt; j++) {
            int s = s_idx[wrp][j];
            float wt = ((const float*)&s_wv[wrp][j])[hl];
            float4 v = *(const float4*)(g_hp + (size_t)s * 128 + lane * 4);
            ax += v.x * wt; ay += v.y * wt; az += v.z * wt; aw += v.w * wt;
        }
        __syncwarp();
    }

#pragma unroll
    for (int o = 16; o > 0; o >>= 1) {
        dl0 += __shfl_xor_sync(0xffffffffu, dl0, o);
        dl1 += __shfl_xor_sync(0xffffffffu, dl1, o);
        dl2 += __shfl_xor_sync(0xffffffffu, dl2, o);
        dl3 += __shfl_xor_sync(0xffffffffu, dl3, o);
    }
    float dh = (hl == 0) ? dl0 : (hl == 1) ? dl1 : (hl == 2) ? dl2 : dl3;
    float inv = 1.f / (dh + 1e-16f);

    const float invsq = rsqrtf(1.0f + 1e-5f);
    float res[4] = {ax * inv, ay * inv, az * inv, aw * inv};
#pragma unroll
    for (int j = 0; j < 4; j++) {
        int c = lane * 4 + j;
        float v = res[j] + bias[c];
        v = v * (gamma[c] * invsq) + beta[c];
        res[j] = (v > 0.f) ? v : expm1f(v);
    }
    *(float4*)(out + (size_t)node * 128 + lane * 4) = make_float4(res[0], res[1], res[2], res[3]);
}

// ---------------- layer 2: GEMM [N,128]@[128,10] fused with attn dots --------
__global__ void k_layer2_gemm_dots(const float* __restrict__ act, const float* __restrict__ W2,
                                   const float* __restrict__ as2, const float* __restrict__ ad2,
                                   int n) {
    __shared__ float W2t[10 * 128];
    __shared__ float s_as[10], s_ad[10];
    int tid = threadIdx.x;
    for (int i = tid; i < 1280; i += 256) {
        int k = i / 10, c = i % 10;
        W2t[c * 128 + k] = W2[i];
    }
    if (tid < 10) { s_as[tid] = as2[tid]; s_ad[tid] = ad2[tid]; }
    __syncthreads();

    int node = (blockIdx.x * blockDim.x + tid) >> 5;
    if (node >= n) return;
    int lane = tid & 31;
    float4 v = *(const float4*)(act + (size_t)node * 128 + lane * 4);
    float as_acc = 0.f, ad_acc = 0.f;
#pragma unroll
    for (int c = 0; c < 10; c++) {
        const float* wc = W2t + c * 128 + lane * 4;
        float p = v.x * wc[0] + v.y * wc[1] + v.z * wc[2] + v.w * wc[3];
#pragma unroll
        for (int o = 16; o > 0; o >>= 1) p += __shfl_xor_sync(0xffffffffu, p, o);
        if (lane == 0) g_hp2[node * 10 + c] = p;
        as_acc += p * s_as[c];
        ad_acc += p * s_ad[c];
    }
    if (lane == 0) { g_as2[node] = as_acc; g_ad2[node] = ad_acc; }
}

// single-pass edge-parallel aggregate for CLS layer
__global__ void k_aggregate10(const float* __restrict__ b2, float* __restrict__ out, int n) {
    int gt = blockIdx.x * blockDim.x + threadIdx.x;
    int node = gt >> 5;
    if (node >= n) return;
    int lane = threadIdx.x & 31;
    int s0 = g_off[node], s1 = g_off[node + 1];
    float adn = g_ad2[node];

    float dsum = 0.f;
    float acc[10];
#pragma unroll
    for (int c = 0; c < 10; c++) acc[c] = 0.f;
    for (int i = s0 + lane; i < s1; i += 32) {
        int s = g_csr[i];
        float w = __expf(leaky(g_as2[s] + adn));
        dsum += w;
        const float2* p = (const float2*)(g_hp2 + s * 10);
#pragma unroll
        for (int c = 0; c < 5; c++) {
            float2 v = p[c];
            acc[2 * c]     += v.x * w;
            acc[2 * c + 1] += v.y * w;
        }
    }
#pragma unroll
    for (int o = 16; o > 0; o >>= 1) {
        dsum += __shfl_xor_sync(0xffffffffu, dsum, o);
#pragma unroll
        for (int c = 0; c < 10; c++)
            acc[c] += __shfl_xor_sync(0xffffffffu, acc[c], o);
    }
    float inv = 1.f / (dsum + 1e-16f);
    if (lane < 10) out[node * 10 + lane] = acc[lane] * inv + b2[lane];
}

// ---------------- launch -----------------------------------------------------
extern "C" void kernel_launch(void* const* d_in, const int* in_sizes, int n_in,
                              void* d_out, int out_size) {
    const float* x   = (const float*)d_in[0];
    const void*  ei  = d_in[1];
    const float* W0  = (const float*)d_in[2];
    const float* as0 = (const float*)d_in[3];
    const float* ad0 = (const float*)d_in[4];
    const float* b0  = (const float*)d_in[5];
    const float* g0  = (const float*)d_in[6];
    const float* be0 = (const float*)d_in[7];
    const float* W1  = (const float*)d_in[8];
    const float* as1 = (const float*)d_in[9];
    const float* ad1 = (const float*)d_in[10];
    const float* b1  = (const float*)d_in[11];
    const float* g1  = (const float*)d_in[12];
    const float* be1 = (const float*)d_in[13];
    const float* W2  = (const float*)d_in[14];
    const float* as2 = (const float*)d_in[15];
    const float* ad2 = (const float*)d_in[16];
    const float* b2  = (const float*)d_in[17];
    float* out = (float*)d_out;

    int E = in_sizes[1] / 2;
    int Etot = E + NN;

    float* hp;    cudaGetSymbolAddress((void**)&hp, g_hp);
    float* actA;  cudaGetSymbolAddress((void**)&actA, g_actA);
    float* actB;  cudaGetSymbolAddress((void**)&actB, g_actB);
    int* degp;    cudaGetSymbolAddress((void**)&degp, g_deg);

    int wpn_grid = (NN + 7) / 8;

    // ---- fork: CSR build on s2, GEMM0 on main stream, join before aggregate0
    cudaEventRecord(g_hx.fork, 0);
    cudaStreamWaitEvent(g_hx.s2, g_hx.fork, 0);

    cudaMemsetAsync(degp, 0, NN * sizeof(int), g_hx.s2);
    k_probe<<<1, 32, 0, g_hx.s2>>>((const int*)ei);
    k_hist<<<(Etot + 255) / 256, 256, 0, g_hx.s2>>>(ei, E, Etot);
    k_scan_a<<<NBLK, 1024, 0, g_hx.s2>>>();
    k_scan_c<<<(NN + 255) / 256, 256, 0, g_hx.s2>>>();
    k_scatter<<<(Etot + 255) / 256, 256, 0, g_hx.s2>>>(ei, E, Etot);
    cudaEventRecord(g_hx.join, g_hx.s2);

    // GEMM0 (main stream, overlaps CSR build)
    k_gemm128<<<GEMM_GRID, 256>>>(x, W0, as0, ad0, hp, NN);

    cudaStreamWaitEvent(0, g_hx.join, 0);

    // ---- layer 0 aggregate ----
    k_aggregate128<<<wpn_grid, 256>>>(b0, g0, be0, actA, NN);

    // ---- layer 1 ----
    k_gemm128<<<GEMM_GRID, 256>>>(actA, W1, as1, ad1, hp, NN);
    k_aggregate128<<<wpn_grid, 256>>>(b1, g1, be1, actB, NN);

    // ---- layer 2 ----
    k_layer2_gemm_dots<<<wpn_grid, 256>>>(actB, W2, as2, ad2, NN);
    k_aggregate10<<<wpn_grid, 256>>>(b2, out, NN);
}

// round 10
// speedup vs baseline: 1.0178x; 1.0178x over previous
#include <cuda_runtime.h>
#include <cuda_bf16.h>
#include <stdint.h>
#include <math.h>

typedef unsigned int u32;

#define NN 50000
#define EMAX 600000
#define ETOT_MAX (EMAX + NN)
#define NBLK ((NN + 1023) / 1024)   // 49

// ---------------- scratch (device globals; no allocations allowed) ----------
__device__ float g_hp[(size_t)NN * 128];
__device__ float g_actA[(size_t)NN * 128];
__device__ float g_actB[(size_t)NN * 128];
__device__ float g_hp2[NN * 10];
__device__ float g_as[NN * 4];
__device__ float g_ad[NN * 4];
__device__ float g_as2[NN];
__device__ float g_ad2[NN];
__device__ int   g_deg[NN];
__device__ int   g_off[NN + 1];
__device__ int   g_cur[NN];
__device__ int   g_csr[ETOT_MAX];
__device__ int   g_bsum[NBLK];
__device__ int   g_is64;

// host-side stream/event resources, created once at program init.
struct HxStreams {
    cudaStream_t s2;
    cudaEvent_t fork, join;
    HxStreams() {
        cudaStreamCreateWithFlags(&s2, cudaStreamNonBlocking);
        cudaEventCreateWithFlags(&fork, cudaEventDisableTiming);
        cudaEventCreateWithFlags(&join, cudaEventDisableTiming);
    }
};
static HxStreams g_hx;

// ---------------- edge-index dtype probe --------------------------------------
__global__ void k_probe(const int* __restrict__ ei32) {
    if (threadIdx.x == 0) {
        int ok = 1;
        for (int e = 0; e < 64; e++)
            if (ei32[2 * e + 1] != 0) { ok = 0; break; }
        g_is64 = ok;
    }
}

__device__ __forceinline__ int load_idx(const void* ei, long long pos) {
    if (g_is64) return (int)((const long long*)ei)[pos];
    return ((const int*)ei)[pos];
}

// ---------------- CSR build --------------------------------------------------
__global__ void k_hist(const void* __restrict__ ei, int E, int Etot) {
    int e = blockIdx.x * blockDim.x + threadIdx.x;
    if (e >= Etot) return;
    int d = (e < E) ? load_idx(ei, (long long)E + e) : (e - E);
    atomicAdd(&g_deg[d], 1);
}

__global__ void k_scan_a() {
    __shared__ int sh[1024];
    int b = blockIdx.x, t = threadIdx.x;
    int i = b * 1024 + t;
    int v = (i < NN) ? g_deg[i] : 0;
    sh[t] = v;
    __syncthreads();
    for (int off = 1; off < 1024; off <<= 1) {
        int u = (t >= off) ? sh[t - off] : 0;
        __syncthreads();
        sh[t] += u;
        __syncthreads();
    }
    if (i < NN) g_off[i] = sh[t] - v;
    if (t == 1023) g_bsum[b] = sh[t];
}

__global__ void k_scan_c() {
    __shared__ int pre[NBLK];
    if (threadIdx.x == 0) {
        int run = 0;
        for (int b = 0; b < NBLK; b++) { pre[b] = run; run += g_bsum[b]; }
        if (blockIdx.x == 0) g_off[NN] = run;
    }
    __syncthreads();
    int i = blockIdx.x * blockDim.x + threadIdx.x;
    if (i >= NN) return;
    int o = g_off[i] + pre[i >> 10];
    g_off[i] = o;
    g_cur[i] = o;
}

__global__ void k_scatter(const void* __restrict__ ei, int E, int Etot) {
    int e = blockIdx.x * blockDim.x + threadIdx.x;
    if (e >= Etot) return;
    int s, d;
    if (e < E) {
        s = load_idx(ei, e);
        d = load_idx(ei, (long long)E + e);
    } else {
        s = d = e - E;
    }
    int pos = atomicAdd(&g_cur[d], 1);
    g_csr[pos] = s;
}

// ---------------- tensor-core GEMM helpers -----------------------------------
__device__ __forceinline__ u32 s2u(const void* p) {
    return (u32)__cvta_generic_to_shared(p);
}
__device__ __forceinline__ void ldsm4(u32& r0, u32& r1, u32& r2, u32& r3, u32 addr) {
    asm volatile("ldmatrix.sync.aligned.m8n8.x4.shared.b16 {%0,%1,%2,%3}, [%4];"
                 : "=r"(r0), "=r"(r1), "=r"(r2), "=r"(r3) : "r"(addr));
}
__device__ __forceinline__ void ldsm4t(u32& r0, u32& r1, u32& r2, u32& r3, u32 addr) {
    asm volatile("ldmatrix.sync.aligned.m8n8.x4.trans.shared.b16 {%0,%1,%2,%3}, [%4];"
                 : "=r"(r0), "=r"(r1), "=r"(r2), "=r"(r3) : "r"(addr));
}
__device__ __forceinline__ void mma16816(float* c, const u32* a, u32 b0, u32 b1) {
    asm volatile(
        "mma.sync.aligned.m16n8k16.row.col.f32.bf16.bf16.f32 "
        "{%0,%1,%2,%3}, {%4,%5,%6,%7}, {%8,%9}, {%0,%1,%2,%3};"
        : "+f"(c[0]), "+f"(c[1]), "+f"(c[2]), "+f"(c[3])
        : "r"(a[0]), "r"(a[1]), "r"(a[2]), "r"(a[3]), "r"(b0), "r"(b1));
}
__device__ __forceinline__ void split4(float4 v, __nv_bfloat16* ph, __nv_bfloat16* pl) {
    __nv_bfloat16 h0 = __float2bfloat16(v.x);
    __nv_bfloat16 h1 = __float2bfloat16(v.y);
    __nv_bfloat16 h2 = __float2bfloat16(v.z);
    __nv_bfloat16 h3 = __float2bfloat16(v.w);
    ph[0] = h0; ph[1] = h1; ph[2] = h2; ph[3] = h3;
    pl[0] = __float2bfloat16(v.x - __bfloat162float(h0));
    pl[1] = __float2bfloat16(v.y - __bfloat162float(h1));
    pl[2] = __float2bfloat16(v.z - __bfloat162float(h2));
    pl[3] = __float2bfloat16(v.w - __bfloat162float(h3));
}

// C[n,128] = A[n,128] @ W[128,128] via bf16x2 split mma + fused attn dots.
#define APAD 40
#define WPAD 136
__global__ void __launch_bounds__(256, 2)
k_gemm128(const float* __restrict__ A, const float* __restrict__ W,
          const float* __restrict__ att_s, const float* __restrict__ att_d,
          float* __restrict__ C, int n) {
    __shared__ __align__(16) __nv_bfloat16 Ah[128][APAD];
    __shared__ __align__(16) __nv_bfloat16 Al[128][APAD];
    __shared__ __align__(16) __nv_bfloat16 Wh[32][WPAD];
    __shared__ __align__(16) __nv_bfloat16 Wl[32][WPAD];

    int tid = threadIdx.x;
    int lane = tid & 31;
    int wid = tid >> 5;
    int warp_m = wid >> 1;
    int warp_n = wid & 1;
    int row0 = blockIdx.x * 128;
    int wrow0 = warp_m * 32;
    int wcol0 = warp_n * 64;

    int a_r = tid >> 3;
    int a_c = (tid & 7) * 4;
    int w_k = tid >> 3;

    float acc[2][8][4];
#pragma unroll
    for (int i = 0; i < 2; i++)
#pragma unroll
        for (int j = 0; j < 8; j++)
#pragma unroll
            for (int q = 0; q < 4; q++) acc[i][j][q] = 0.f;

    float4 pa[4], pw[4];
#pragma unroll
    for (int it = 0; it < 4; it++) {
        int grow = row0 + a_r + it * 32;
        pa[it] = make_float4(0.f, 0.f, 0.f, 0.f);
        if (grow < n) pa[it] = *(const float4*)(A + (size_t)grow * 128 + a_c);
        pw[it] = *(const float4*)(W + (size_t)w_k * 128 + (tid & 7) * 4 + it * 32);
    }

    for (int k0 = 0; k0 < 128; k0 += 32) {
#pragma unroll
        for (int it = 0; it < 4; it++) {
            int r = a_r + it * 32;
            split4(pa[it], &Ah[r][a_c], &Al[r][a_c]);
            int c = (tid & 7) * 4 + it * 32;
            split4(pw[it], &Wh[w_k][c], &Wl[w_k][c]);
        }
        __syncthreads();

        if (k0 + 32 < 128) {
#pragma unroll
            for (int it = 0; it < 4; it++) {
                int grow = row0 + a_r + it * 32;
                pa[it] = make_float4(0.f, 0.f, 0.f, 0.f);
                if (grow < n) pa[it] = *(const float4*)(A + (size_t)grow * 128 + k0 + 32 + a_c);
                pw[it] = *(const float4*)(W + (size_t)(k0 + 32 + w_k) * 128 + (tid & 7) * 4 + it * 32);
            }
        }

#pragma unroll
        for (int ks = 0; ks < 32; ks += 16) {
            u32 ah[2][4], al[2][4], bb[4][4];
            int arow = (lane & 15);
            int acol = ks + ((lane >> 4) << 3);
#pragma unroll
            for (int mt = 0; mt < 2; mt++)
                ldsm4(ah[mt][0], ah[mt][1], ah[mt][2], ah[mt][3],
                      s2u(&Ah[wrow0 + mt * 16 + arow][acol]));
#pragma unroll
            for (int p = 0; p < 4; p++) {
                int j = p * 2 + (lane >> 4);
                ldsm4t(bb[p][0], bb[p][1], bb[p][2], bb[p][3],
                       s2u(&Wh[ks + (lane & 15)][wcol0 + j * 8]));
            }
#pragma unroll
            for (int mt = 0; mt < 2; mt++)
#pragma unroll
                for (int j = 0; j < 8; j++)
                    mma16816(acc[mt][j], ah[mt], bb[j >> 1][(j & 1) * 2], bb[j >> 1][(j & 1) * 2 + 1]);
#pragma unroll
            for (int mt = 0; mt < 2; mt++)
                ldsm4(al[mt][0], al[mt][1], al[mt][2], al[mt][3],
                      s2u(&Al[wrow0 + mt * 16 + arow][acol]));
#pragma unroll
            for (int mt = 0; mt < 2; mt++)
#pragma unroll
                for (int j = 0; j < 8; j++)
                    mma16816(acc[mt][j], al[mt], bb[j >> 1][(j & 1) * 2], bb[j >> 1][(j & 1) * 2 + 1]);
#pragma unroll
            for (int p = 0; p < 4; p++) {
                int j = p * 2 + (lane >> 4);
                ldsm4t(bb[p][0], bb[p][1], bb[p][2], bb[p][3],
                       s2u(&Wl[ks + (lane & 15)][wcol0 + j * 8]));
            }
#pragma unroll
            for (int mt = 0; mt < 2; mt++)
#pragma unroll
                for (int j = 0; j < 8; j++)
                    mma16816(acc[mt][j], ah[mt], bb[j >> 1][(j & 1) * 2], bb[j >> 1][(j & 1) * 2 + 1]);
        }
        __syncthreads();
    }

    float2 vs[8], vd[8];
#pragma unroll
    for (int j = 0; j < 8; j++) {
        int col = wcol0 + j * 8 + (lane & 3) * 2;
        vs[j] = *(const float2*)(att_s + col);
        vd[j] = *(const float2*)(att_d + col);
    }

#pragma unroll
    for (int mt = 0; mt < 2; mt++) {
        int r0 = row0 + wrow0 + mt * 16 + (lane >> 2);
        int r1 = r0 + 8;
        float ps0[2] = {0.f, 0.f}, ps1[2] = {0.f, 0.f};
        float pd0[2] = {0.f, 0.f}, pd1[2] = {0.f, 0.f};
#pragma unroll
        for (int j = 0; j < 8; j++) {
            int cofs = wcol0 + j * 8 + (lane & 3) * 2;
            if (r0 < n)
                *(float2*)(C + (size_t)r0 * 128 + cofs) = make_float2(acc[mt][j][0], acc[mt][j][1]);
            if (r1 < n)
                *(float2*)(C + (size_t)r1 * 128 + cofs) = make_float2(acc[mt][j][2], acc[mt][j][3]);
            int h = j >> 2;
            ps0[h] += acc[mt][j][0] * vs[j].x + acc[mt][j][1] * vs[j].y;
            ps1[h] += acc[mt][j][2] * vs[j].x + acc[mt][j][3] * vs[j].y;
            pd0[h] += acc[mt][j][0] * vd[j].x + acc[mt][j][1] * vd[j].y;
            pd1[h] += acc[mt][j][2] * vd[j].x + acc[mt][j][3] * vd[j].y;
        }
#pragma unroll
        for (int o = 1; o <= 2; o <<= 1) {
#pragma unroll
            for (int h = 0; h < 2; h++) {
                ps0[h] += __shfl_xor_sync(0xffffffffu, ps0[h], o);
                ps1[h] += __shfl_xor_sync(0xffffffffu, ps1[h], o);
                pd0[h] += __shfl_xor_sync(0xffffffffu, pd0[h], o);
                pd1[h] += __shfl_xor_sync(0xffffffffu, pd1[h], o);
            }
        }
        if ((lane & 3) == 0) {
#pragma unroll
            for (int h = 0; h < 2; h++) {
                int hd = warp_n * 2 + h;
                if (r0 < n) { g_as[r0 * 4 + hd] = ps0[h]; g_ad[r0 * 4 + hd] = pd0[h]; }
                if (r1 < n) { g_as[r1 * 4 + hd] = ps1[h]; g_ad[r1 * 4 + hd] = pd1[h]; }
            }
        }
    }
}

__device__ __forceinline__ float leaky(float x) { return x > 0.f ? x : 0.2f * x; }

// ---------------- single-pass segment softmax + aggregate + bias/BN/ELU ------
#define CHUNK 64
__global__ void k_aggregate128(const float* __restrict__ bias, const float* __restrict__ gamma,
                               const float* __restrict__ beta, float* __restrict__ out, int n) {
    __shared__ float4 s_wv[8][CHUNK];
    __shared__ int    s_idx[8][CHUNK];
    int gt = blockIdx.x * blockDim.x + threadIdx.x;
    int node = gt >> 5;
    if (node >= n) return;
    int lane = threadIdx.x & 31;
    int wrp = (threadIdx.x >> 5);
    int s0 = g_off[node], s1 = g_off[node + 1];

    float ad0 = g_ad[node * 4 + 0], ad1 = g_ad[node * 4 + 1];
    float ad2 = g_ad[node * 4 + 2], ad3 = g_ad[node * 4 + 3];

    int hl = lane >> 3;
    float dl0 = 0.f, dl1 = 0.f, dl2 = 0.f, dl3 = 0.f;
    float ax = 0.f, ay = 0.f, az = 0.f, aw = 0.f;

    for (int c0 = s0; c0 < s1; c0 += CHUNK) {
        int cnt = min(CHUNK, s1 - c0);
        for (int i = lane; i < cnt; i += 32) {
            int s = g_csr[c0 + i];
            float4 av = *(const float4*)(g_as + s * 4);
            float4 wv;
            wv.x = __expf(leaky(av.x + ad0));
            wv.y = __expf(leaky(av.y + ad1));
            wv.z = __expf(leaky(av.z + ad2));
            wv.w = __expf(leaky(av.w + ad3));
            dl0 += wv.x; dl1 += wv.y; dl2 += wv.z; dl3 += wv.w;
            s_wv[wrp][i] = wv;
            s_idx[wrp][i] = s;
        }
        __syncwarp();
        // gather+accumulate: deep unroll -> 8 outstanding LDG.128 per lane
#pragma unroll 8
        for (int j = 0; j < cnt; j++) {
            int s = s_idx[wrp][j];
            float wt = ((const float*)&s_wv[wrp][j])[hl];
            float4 v = *(const float4*)(g_hp + (size_t)s * 128 + lane * 4);
            ax += v.x * wt; ay += v.y * wt; az += v.z * wt; aw += v.w * wt;
        }
        __syncwarp();
    }

#pragma unroll
    for (int o = 16; o > 0; o >>= 1) {
        dl0 += __shfl_xor_sync(0xffffffffu, dl0, o);
        dl1 += __shfl_xor_sync(0xffffffffu, dl1, o);
        dl2 += __shfl_xor_sync(0xffffffffu, dl2, o);
        dl3 += __shfl_xor_sync(0xffffffffu, dl3, o);
    }
    float dh = (hl == 0) ? dl0 : (hl == 1) ? dl1 : (hl == 2) ? dl2 : dl3;
    float inv = 1.f / (dh + 1e-16f);

    const float invsq = rsqrtf(1.0f + 1e-5f);
    float res[4] = {ax * inv, ay * inv, az * inv, aw * inv};
#pragma unroll
    for (int j = 0; j < 4; j++) {
        int c = lane * 4 + j;
        float v = res[j] + bias[c];
        v = v * (gamma[c] * invsq) + beta[c];
        res[j] = (v > 0.f) ? v : expm1f(v);
    }
    *(float4*)(out + (size_t)node * 128 + lane * 4) = make_float4(res[0], res[1], res[2], res[3]);
}

// ---------------- layer 2: GEMM [N,128]@[128,10] fused with attn dots --------
__global__ void k_layer2_gemm_dots(const float* __restrict__ act, const float* __restrict__ W2,
                                   const float* __restrict__ as2, const float* __restrict__ ad2,
                                   int n) {
    __shared__ float W2t[10 * 128];
    __shared__ float s_as[10], s_ad[10];
    int tid = threadIdx.x;
    for (int i = tid; i < 1280; i += 256) {
        int k = i / 10, c = i % 10;
        W2t[c * 128 + k] = W2[i];
    }
    if (tid < 10) { s_as[tid] = as2[tid]; s_ad[tid] = ad2[tid]; }
    __syncthreads();

    int node = (blockIdx.x * blockDim.x + tid) >> 5;
    if (node >= n) return;
    int lane = tid & 31;
    float4 v = *(const float4*)(act + (size_t)node * 128 + lane * 4);
    float as_acc = 0.f, ad_acc = 0.f;
#pragma unroll
    for (int c = 0; c < 10; c++) {
        const float* wc = W2t + c * 128 + lane * 4;
        float p = v.x * wc[0] + v.y * wc[1] + v.z * wc[2] + v.w * wc[3];
#pragma unroll
        for (int o = 16; o > 0; o >>= 1) p += __shfl_xor_sync(0xffffffffu, p, o);
        if (lane == 0) g_hp2[node * 10 + c] = p;
        as_acc += p * s_as[c];
        ad_acc += p * s_ad[c];
    }
    if (lane == 0) { g_as2[node] = as_acc; g_ad2[node] = ad_acc; }
}

// single-pass edge-parallel aggregate for CLS layer
__global__ void k_aggregate10(const float* __restrict__ b2, float* __restrict__ out, int n) {
    int gt = blockIdx.x * blockDim.x + threadIdx.x;
    int node = gt >> 5;
    if (node >= n) return;
    int lane = threadIdx.x & 31;
    int s0 = g_off[node], s1 = g_off[node + 1];
    float adn = g_ad2[node];

    float dsum = 0.f;
    float acc[10];
#pragma unroll
    for (int c = 0; c < 10; c++) acc[c] = 0.f;
#pragma unroll 2
    for (int i = s0 + lane; i < s1; i += 32) {
        int s = g_csr[i];
        float w = __expf(leaky(g_as2[s] + adn));
        dsum += w;
        const float2* p = (const float2*)(g_hp2 + s * 10);
#pragma unroll
        for (int c = 0; c < 5; c++) {
            float2 v = p[c];
            acc[2 * c]     += v.x * w;
            acc[2 * c + 1] += v.y * w;
        }
    }
#pragma unroll
    for (int o = 16; o > 0; o >>= 1) {
        dsum += __shfl_xor_sync(0xffffffffu, dsum, o);
#pragma unroll
        for (int c = 0; c < 10; c++)
            acc[c] += __shfl_xor_sync(0xffffffffu, acc[c], o);
    }
    float inv = 1.f / (dsum + 1e-16f);
    if (lane < 10) out[node * 10 + lane] = acc[lane] * inv + b2[lane];
}

// ---------------- launch -----------------------------------------------------
extern "C" void kernel_launch(void* const* d_in, const int* in_sizes, int n_in,
                              void* d_out, int out_size) {
    const float* x   = (const float*)d_in[0];
    const void*  ei  = d_in[1];
    const float* W0  = (const float*)d_in[2];
    const float* as0 = (const float*)d_in[3];
    const float* ad0 = (const float*)d_in[4];
    const float* b0  = (const float*)d_in[5];
    const float* g0  = (const float*)d_in[6];
    const float* be0 = (const float*)d_in[7];
    const float* W1  = (const float*)d_in[8];
    const float* as1 = (const float*)d_in[9];
    const float* ad1 = (const float*)d_in[10];
    const float* b1  = (const float*)d_in[11];
    const float* g1  = (const float*)d_in[12];
    const float* be1 = (const float*)d_in[13];
    const float* W2  = (const float*)d_in[14];
    const float* as2 = (const float*)d_in[15];
    const float* ad2 = (const float*)d_in[16];
    const float* b2  = (const float*)d_in[17];
    float* out = (float*)d_out;

    int E = in_sizes[1] / 2;
    int Etot = E + NN;

    float* hp;    cudaGetSymbolAddress((void**)&hp, g_hp);
    float* actA;  cudaGetSymbolAddress((void**)&actA, g_actA);
    float* actB;  cudaGetSymbolAddress((void**)&actB, g_actB);
    int* degp;    cudaGetSymbolAddress((void**)&degp, g_deg);

    int gemm_grid = (NN + 127) / 128;
    int wpn_grid = (NN + 7) / 8;

    // ---- fork: CSR build on s2, GEMM0 on main stream, join before aggregate0
    cudaEventRecord(g_hx.fork, 0);
    cudaStreamWaitEvent(g_hx.s2, g_hx.fork, 0);

    cudaMemsetAsync(degp, 0, NN * sizeof(int), g_hx.s2);
    k_probe<<<1, 32, 0, g_hx.s2>>>((const int*)ei);
    k_hist<<<(Etot + 255) / 256, 256, 0, g_hx.s2>>>(ei, E, Etot);
    k_scan_a<<<NBLK, 1024, 0, g_hx.s2>>>();
    k_scan_c<<<(NN + 255) / 256, 256, 0, g_hx.s2>>>();
    k_scatter<<<(Etot + 255) / 256, 256, 0, g_hx.s2>>>(ei, E, Etot);
    cudaEventRecord(g_hx.join, g_hx.s2);

    // GEMM0 (main stream, overlaps CSR build)
    k_gemm128<<<gemm_grid, 256>>>(x, W0, as0, ad0, hp, NN);

    cudaStreamWaitEvent(0, g_hx.join, 0);

    // ---- layer 0 aggregate ----
    k_aggregate128<<<wpn_grid, 256>>>(b0, g0, be0, actA, NN);

    // ---- layer 1 ----
    k_gemm128<<<gemm_grid, 256>>>(actA, W1, as1, ad1, hp, NN);
    k_aggregate128<<<wpn_grid, 256>>>(b1, g1, be1, actB, NN);

    // ---- layer 2 ----
    k_layer2_gemm_dots<<<wpn_grid, 256>>>(actB, W2, as2, ad2, NN);
    k_aggregate10<<<wpn_grid, 256>>>(b2, out, NN);
}

// round 11
// speedup vs baseline: 1.0818x; 1.0630x over previous
#include <cuda_runtime.h>
#include <cuda_bf16.h>
#include <cuda_fp16.h>
#include <stdint.h>
#include <math.h>

typedef unsigned int u32;

#define NN 50000
#define EMAX 600000
#define ETOT_MAX (EMAX + NN)
#define NBLK ((NN + 1023) / 1024)   // 49

// ---------------- scratch (device globals; no allocations allowed) ----------
__device__ __half g_hp[(size_t)NN * 128];    // fp16 messages (weights stay fp32)
__device__ float g_actA[(size_t)NN * 128];
__device__ float g_actB[(size_t)NN * 128];
__device__ float g_hp2[NN * 10];
__device__ float g_as[NN * 4];
__device__ float g_ad[NN * 4];
__device__ float g_as2[NN];
__device__ float g_ad2[NN];
__device__ int   g_deg[NN];
__device__ int   g_off[NN + 1];
__device__ int   g_cur[NN];
__device__ int   g_csr[ETOT_MAX];
__device__ int   g_bsum[NBLK];
__device__ int   g_is64;

// host-side stream/event resources, created once at program init.
struct HxStreams {
    cudaStream_t s2;
    cudaEvent_t fork, join;
    HxStreams() {
        cudaStreamCreateWithFlags(&s2, cudaStreamNonBlocking);
        cudaEventCreateWithFlags(&fork, cudaEventDisableTiming);
        cudaEventCreateWithFlags(&join, cudaEventDisableTiming);
    }
};
static HxStreams g_hx;

// ---------------- edge-index dtype probe --------------------------------------
__global__ void k_probe(const int* __restrict__ ei32) {
    if (threadIdx.x == 0) {
        int ok = 1;
        for (int e = 0; e < 64; e++)
            if (ei32[2 * e + 1] != 0) { ok = 0; break; }
        g_is64 = ok;
    }
}

__device__ __forceinline__ int load_idx(const void* ei, long long pos) {
    if (g_is64) return (int)((const long long*)ei)[pos];
    return ((const int*)ei)[pos];
}

// ---------------- CSR build --------------------------------------------------
__global__ void k_hist(const void* __restrict__ ei, int E, int Etot) {
    int e = blockIdx.x * blockDim.x + threadIdx.x;
    if (e >= Etot) return;
    int d = (e < E) ? load_idx(ei, (long long)E + e) : (e - E);
    atomicAdd(&g_deg[d], 1);
}

__global__ void k_scan_a() {
    __shared__ int sh[1024];
    int b = blockIdx.x, t = threadIdx.x;
    int i = b * 1024 + t;
    int v = (i < NN) ? g_deg[i] : 0;
    sh[t] = v;
    __syncthreads();
    for (int off = 1; off < 1024; off <<= 1) {
        int u = (t >= off) ? sh[t - off] : 0;
        __syncthreads();
        sh[t] += u;
        __syncthreads();
    }
    if (i < NN) g_off[i] = sh[t] - v;
    if (t == 1023) g_bsum[b] = sh[t];
}

__global__ void k_scan_c() {
    __shared__ int pre[NBLK];
    if (threadIdx.x == 0) {
        int run = 0;
        for (int b = 0; b < NBLK; b++) { pre[b] = run; run += g_bsum[b]; }
        if (blockIdx.x == 0) g_off[NN] = run;
    }
    __syncthreads();
    int i = blockIdx.x * blockDim.x + threadIdx.x;
    if (i >= NN) return;
    int o = g_off[i] + pre[i >> 10];
    g_off[i] = o;
    g_cur[i] = o;
}

__global__ void k_scatter(const void* __restrict__ ei, int E, int Etot) {
    int e = blockIdx.x * blockDim.x + threadIdx.x;
    if (e >= Etot) return;
    int s, d;
    if (e < E) {
        s = load_idx(ei, e);
        d = load_idx(ei, (long long)E + e);
    } else {
        s = d = e - E;
    }
    int pos = atomicAdd(&g_cur[d], 1);
    g_csr[pos] = s;
}

// ---------------- tensor-core GEMM helpers -----------------------------------
__device__ __forceinline__ u32 s2u(const void* p) {
    return (u32)__cvta_generic_to_shared(p);
}
__device__ __forceinline__ void ldsm4(u32& r0, u32& r1, u32& r2, u32& r3, u32 addr) {
    asm volatile("ldmatrix.sync.aligned.m8n8.x4.shared.b16 {%0,%1,%2,%3}, [%4];"
                 : "=r"(r0), "=r"(r1), "=r"(r2), "=r"(r3) : "r"(addr));
}
__device__ __forceinline__ void ldsm4t(u32& r0, u32& r1, u32& r2, u32& r3, u32 addr) {
    asm volatile("ldmatrix.sync.aligned.m8n8.x4.trans.shared.b16 {%0,%1,%2,%3}, [%4];"
                 : "=r"(r0), "=r"(r1), "=r"(r2), "=r"(r3) : "r"(addr));
}
__device__ __forceinline__ void mma16816(float* c, const u32* a, u32 b0, u32 b1) {
    asm volatile(
        "mma.sync.aligned.m16n8k16.row.col.f32.bf16.bf16.f32 "
        "{%0,%1,%2,%3}, {%4,%5,%6,%7}, {%8,%9}, {%0,%1,%2,%3};"
        : "+f"(c[0]), "+f"(c[1]), "+f"(c[2]), "+f"(c[3])
        : "r"(a[0]), "r"(a[1]), "r"(a[2]), "r"(a[3]), "r"(b0), "r"(b1));
}
__device__ __forceinline__ void split4(float4 v, __nv_bfloat16* ph, __nv_bfloat16* pl) {
    __nv_bfloat16 h0 = __float2bfloat16(v.x);
    __nv_bfloat16 h1 = __float2bfloat16(v.y);
    __nv_bfloat16 h2 = __float2bfloat16(v.z);
    __nv_bfloat16 h3 = __float2bfloat16(v.w);
    ph[0] = h0; ph[1] = h1; ph[2] = h2; ph[3] = h3;
    pl[0] = __float2bfloat16(v.x - __bfloat162float(h0));
    pl[1] = __float2bfloat16(v.y - __bfloat162float(h1));
    pl[2] = __float2bfloat16(v.z - __bfloat162float(h2));
    pl[3] = __float2bfloat16(v.w - __bfloat162float(h3));
}

// C(fp16)[n,128] = A[n,128] @ W[128,128] via bf16x2 split mma + fused attn dots.
#define APAD 40
#define WPAD 136
__global__ void __launch_bounds__(256, 2)
k_gemm128(const float* __restrict__ A, const float* __restrict__ W,
          const float* __restrict__ att_s, const float* __restrict__ att_d,
          __half* __restrict__ C, int n) {
    __shared__ __align__(16) __nv_bfloat16 Ah[128][APAD];
    __shared__ __align__(16) __nv_bfloat16 Al[128][APAD];
    __shared__ __align__(16) __nv_bfloat16 Wh[32][WPAD];
    __shared__ __align__(16) __nv_bfloat16 Wl[32][WPAD];

    int tid = threadIdx.x;
    int lane = tid & 31;
    int wid = tid >> 5;
    int warp_m = wid >> 1;
    int warp_n = wid & 1;
    int row0 = blockIdx.x * 128;
    int wrow0 = warp_m * 32;
    int wcol0 = warp_n * 64;

    int a_r = tid >> 3;
    int a_c = (tid & 7) * 4;
    int w_k = tid >> 3;

    float acc[2][8][4];
#pragma unroll
    for (int i = 0; i < 2; i++)
#pragma unroll
        for (int j = 0; j < 8; j++)
#pragma unroll
            for (int q = 0; q < 4; q++) acc[i][j][q] = 0.f;

    float4 pa[4], pw[4];
#pragma unroll
    for (int it = 0; it < 4; it++) {
        int grow = row0 + a_r + it * 32;
        pa[it] = make_float4(0.f, 0.f, 0.f, 0.f);
        if (grow < n) pa[it] = *(const float4*)(A + (size_t)grow * 128 + a_c);
        pw[it] = *(const float4*)(W + (size_t)w_k * 128 + (tid & 7) * 4 + it * 32);
    }

    for (int k0 = 0; k0 < 128; k0 += 32) {
#pragma unroll
        for (int it = 0; it < 4; it++) {
            int r = a_r + it * 32;
            split4(pa[it], &Ah[r][a_c], &Al[r][a_c]);
            int c = (tid & 7) * 4 + it * 32;
            split4(pw[it], &Wh[w_k][c], &Wl[w_k][c]);
        }
        __syncthreads();

        if (k0 + 32 < 128) {
#pragma unroll
            for (int it = 0; it < 4; it++) {
                int grow = row0 + a_r + it * 32;
                pa[it] = make_float4(0.f, 0.f, 0.f, 0.f);
                if (grow < n) pa[it] = *(const float4*)(A + (size_t)grow * 128 + k0 + 32 + a_c);
                pw[it] = *(const float4*)(W + (size_t)(k0 + 32 + w_k) * 128 + (tid & 7) * 4 + it * 32);
            }
        }

#pragma unroll
        for (int ks = 0; ks < 32; ks += 16) {
            u32 ah[2][4], al[2][4], bb[4][4];
            int arow = (lane & 15);
            int acol = ks + ((lane >> 4) << 3);
#pragma unroll
            for (int mt = 0; mt < 2; mt++)
                ldsm4(ah[mt][0], ah[mt][1], ah[mt][2], ah[mt][3],
                      s2u(&Ah[wrow0 + mt * 16 + arow][acol]));
#pragma unroll
            for (int p = 0; p < 4; p++) {
                int j = p * 2 + (lane >> 4);
                ldsm4t(bb[p][0], bb[p][1], bb[p][2], bb[p][3],
                       s2u(&Wh[ks + (lane & 15)][wcol0 + j * 8]));
            }
#pragma unroll
            for (int mt = 0; mt < 2; mt++)
#pragma unroll
                for (int j = 0; j < 8; j++)
                    mma16816(acc[mt][j], ah[mt], bb[j >> 1][(j & 1) * 2], bb[j >> 1][(j & 1) * 2 + 1]);
#pragma unroll
            for (int mt = 0; mt < 2; mt++)
                ldsm4(al[mt][0], al[mt][1], al[mt][2], al[mt][3],
                      s2u(&Al[wrow0 + mt * 16 + arow][acol]));
#pragma unroll
            for (int mt = 0; mt < 2; mt++)
#pragma unroll
                for (int j = 0; j < 8; j++)
                    mma16816(acc[mt][j], al[mt], bb[j >> 1][(j & 1) * 2], bb[j >> 1][(j & 1) * 2 + 1]);
#pragma unroll
            for (int p = 0; p < 4; p++) {
                int j = p * 2 + (lane >> 4);
                ldsm4t(bb[p][0], bb[p][1], bb[p][2], bb[p][3],
                       s2u(&Wl[ks + (lane & 15)][wcol0 + j * 8]));
            }
#pragma unroll
            for (int mt = 0; mt < 2; mt++)
#pragma unroll
                for (int j = 0; j < 8; j++)
                    mma16816(acc[mt][j], ah[mt], bb[j >> 1][(j & 1) * 2], bb[j >> 1][(j & 1) * 2 + 1]);
        }
        __syncthreads();
    }

    float2 vs[8], vd[8];
#pragma unroll
    for (int j = 0; j < 8; j++) {
        int col = wcol0 + j * 8 + (lane & 3) * 2;
        vs[j] = *(const float2*)(att_s + col);
        vd[j] = *(const float2*)(att_d + col);
    }

#pragma unroll
    for (int mt = 0; mt < 2; mt++) {
        int r0 = row0 + wrow0 + mt * 16 + (lane >> 2);
        int r1 = r0 + 8;
        float ps0[2] = {0.f, 0.f}, ps1[2] = {0.f, 0.f};
        float pd0[2] = {0.f, 0.f}, pd1[2] = {0.f, 0.f};
#pragma unroll
        for (int j = 0; j < 8; j++) {
            int cofs = wcol0 + j * 8 + (lane & 3) * 2;
            if (r0 < n)
                *(__half2*)(C + (size_t)r0 * 128 + cofs) =
                    __floats2half2_rn(acc[mt][j][0], acc[mt][j][1]);
            if (r1 < n)
                *(__half2*)(C + (size_t)r1 * 128 + cofs) =
                    __floats2half2_rn(acc[mt][j][2], acc[mt][j][3]);
            int h = j >> 2;
            ps0[h] += acc[mt][j][0] * vs[j].x + acc[mt][j][1] * vs[j].y;
            ps1[h] += acc[mt][j][2] * vs[j].x + acc[mt][j][3] * vs[j].y;
            pd0[h] += acc[mt][j][0] * vd[j].x + acc[mt][j][1] * vd[j].y;
            pd1[h] += acc[mt][j][2] * vd[j].x + acc[mt][j][3] * vd[j].y;
        }
#pragma unroll
        for (int o = 1; o <= 2; o <<= 1) {
#pragma unroll
            for (int h = 0; h < 2; h++) {
                ps0[h] += __shfl_xor_sync(0xffffffffu, ps0[h], o);
                ps1[h] += __shfl_xor_sync(0xffffffffu, ps1[h], o);
                pd0[h] += __shfl_xor_sync(0xffffffffu, pd0[h], o);
                pd1[h] += __shfl_xor_sync(0xffffffffu, pd1[h], o);
            }
        }
        if ((lane & 3) == 0) {
#pragma unroll
            for (int h = 0; h < 2; h++) {
                int hd = warp_n * 2 + h;
                if (r0 < n) { g_as[r0 * 4 + hd] = ps0[h]; g_ad[r0 * 4 + hd] = pd0[h]; }
                if (r1 < n) { g_as[r1 * 4 + hd] = ps1[h]; g_ad[r1 * 4 + hd] = pd1[h]; }
            }
        }
    }
}

__device__ __forceinline__ float leaky(float x) { return x > 0.f ? x : 0.2f * x; }

// ---------------- single-pass segment softmax + aggregate + bias/BN/ELU ------
// Messages gathered in fp16 (half traffic); weights/denoms in fp32.
#define CHUNK 64
__global__ void k_aggregate128(const float* __restrict__ bias, const float* __restrict__ gamma,
                               const float* __restrict__ beta, float* __restrict__ out, int n) {
    __shared__ float4 s_wv[8][CHUNK];
    __shared__ int    s_idx[8][CHUNK];
    int gt = blockIdx.x * blockDim.x + threadIdx.x;
    int node = gt >> 5;
    if (node >= n) return;
    int lane = threadIdx.x & 31;
    int wrp = (threadIdx.x >> 5);
    int s0 = g_off[node], s1 = g_off[node + 1];

    float ad0 = g_ad[node * 4 + 0], ad1 = g_ad[node * 4 + 1];
    float ad2 = g_ad[node * 4 + 2], ad3 = g_ad[node * 4 + 3];

    int hl = lane >> 3;
    float dl0 = 0.f, dl1 = 0.f, dl2 = 0.f, dl3 = 0.f;
    float ax = 0.f, ay = 0.f, az = 0.f, aw = 0.f;

    for (int c0 = s0; c0 < s1; c0 += CHUNK) {
        int cnt = min(CHUNK, s1 - c0);
        for (int i = lane; i < cnt; i += 32) {
            int s = g_csr[c0 + i];
            float4 av = *(const float4*)(g_as + s * 4);
            float4 wv;
            wv.x = __expf(leaky(av.x + ad0));
            wv.y = __expf(leaky(av.y + ad1));
            wv.z = __expf(leaky(av.z + ad2));
            wv.w = __expf(leaky(av.w + ad3));
            dl0 += wv.x; dl1 += wv.y; dl2 += wv.z; dl3 += wv.w;
            s_wv[wrp][i] = wv;
            s_idx[wrp][i] = s;
        }
        __syncwarp();
        // gather fp16 messages: one 8B load per edge per lane
#pragma unroll 4
        for (int j = 0; j < cnt; j++) {
            int s = s_idx[wrp][j];
            float wt = ((const float*)&s_wv[wrp][j])[hl];
            const __half2* p = (const __half2*)(g_hp + (size_t)s * 128 + lane * 4);
            float2 v01 = __half22float2(p[0]);
            float2 v23 = __half22float2(p[1]);
            ax += v01.x * wt; ay += v01.y * wt; az += v23.x * wt; aw += v23.y * wt;
        }
        __syncwarp();
    }

#pragma unroll
    for (int o = 16; o > 0; o >>= 1) {
        dl0 += __shfl_xor_sync(0xffffffffu, dl0, o);
        dl1 += __shfl_xor_sync(0xffffffffu, dl1, o);
        dl2 += __shfl_xor_sync(0xffffffffu, dl2, o);
        dl3 += __shfl_xor_sync(0xffffffffu, dl3, o);
    }
    float dh = (hl == 0) ? dl0 : (hl == 1) ? dl1 : (hl == 2) ? dl2 : dl3;
    float inv = 1.f / (dh + 1e-16f);

    const float invsq = rsqrtf(1.0f + 1e-5f);
    float res[4] = {ax * inv, ay * inv, az * inv, aw * inv};
#pragma unroll
    for (int j = 0; j < 4; j++) {
        int c = lane * 4 + j;
        float v = res[j] + bias[c];
        v = v * (gamma[c] * invsq) + beta[c];
        res[j] = (v > 0.f) ? v : expm1f(v);
    }
    *(float4*)(out + (size_t)node * 128 + lane * 4) = make_float4(res[0], res[1], res[2], res[3]);
}

// ---------------- layer 2: GEMM [N,128]@[128,10] fused with attn dots --------
__global__ void k_layer2_gemm_dots(const float* __restrict__ act, const float* __restrict__ W2,
                                   const float* __restrict__ as2, const float* __restrict__ ad2,
                                   int n) {
    __shared__ float W2t[10 * 128];
    __shared__ float s_as[10], s_ad[10];
    int tid = threadIdx.x;
    for (int i = tid; i < 1280; i += 256) {
        int k = i / 10, c = i % 10;
        W2t[c * 128 + k] = W2[i];
    }
    if (tid < 10) { s_as[tid] = as2[tid]; s_ad[tid] = ad2[tid]; }
    __syncthreads();

    int node = (blockIdx.x * blockDim.x + tid) >> 5;
    if (node >= n) return;
    int lane = tid & 31;
    float4 v = *(const float4*)(act + (size_t)node * 128 + lane * 4);
    float as_acc = 0.f, ad_acc = 0.f;
#pragma unroll
    for (int c = 0; c < 10; c++) {
        const float* wc = W2t + c * 128 + lane * 4;
        float p = v.x * wc[0] + v.y * wc[1] + v.z * wc[2] + v.w * wc[3];
#pragma unroll
        for (int o = 16; o > 0; o >>= 1) p += __shfl_xor_sync(0xffffffffu, p, o);
        if (lane == 0) g_hp2[node * 10 + c] = p;
        as_acc += p * s_as[c];
        ad_acc += p * s_ad[c];
    }
    if (lane == 0) { g_as2[node] = as_acc; g_ad2[node] = ad_acc; }
}

// single-pass edge-parallel aggregate for CLS layer
__global__ void k_aggregate10(const float* __restrict__ b2, float* __restrict__ out, int n) {
    int gt = blockIdx.x * blockDim.x + threadIdx.x;
    int node = gt >> 5;
    if (node >= n) return;
    int lane = threadIdx.x & 31;
    int s0 = g_off[node], s1 = g_off[node + 1];
    float adn = g_ad2[node];

    float dsum = 0.f;
    float acc[10];
#pragma unroll
    for (int c = 0; c < 10; c++) acc[c] = 0.f;
    for (int i = s0 + lane; i < s1; i += 32) {
        int s = g_csr[i];
        float w = __expf(leaky(g_as2[s] + adn));
        dsum += w;
        const float2* p = (const float2*)(g_hp2 + s * 10);
#pragma unroll
        for (int c = 0; c < 5; c++) {
            float2 v = p[c];
            acc[2 * c]     += v.x * w;
            acc[2 * c + 1] += v.y * w;
        }
    }
#pragma unroll
    for (int o = 16; o > 0; o >>= 1) {
        dsum += __shfl_xor_sync(0xffffffffu, dsum, o);
#pragma unroll
        for (int c = 0; c < 10; c++)
            acc[c] += __shfl_xor_sync(0xffffffffu, acc[c], o);
    }
    float inv = 1.f / (dsum + 1e-16f);
    if (lane < 10) out[node * 10 + lane] = acc[lane] * inv + b2[lane];
}

// ---------------- launch -----------------------------------------------------
extern "C" void kernel_launch(void* const* d_in, const int* in_sizes, int n_in,
                              void* d_out, int out_size) {
    const float* x   = (const float*)d_in[0];
    const void*  ei  = d_in[1];
    const float* W0  = (const float*)d_in[2];
    const float* as0 = (const float*)d_in[3];
    const float* ad0 = (const float*)d_in[4];
    const float* b0  = (const float*)d_in[5];
    const float* g0  = (const float*)d_in[6];
    const float* be0 = (const float*)d_in[7];
    const float* W1  = (const float*)d_in[8];
    const float* as1 = (const float*)d_in[9];
    const float* ad1 = (const float*)d_in[10];
    const float* b1  = (const float*)d_in[11];
    const float* g1  = (const float*)d_in[12];
    const float* be1 = (const float*)d_in[13];
    const float* W2  = (const float*)d_in[14];
    const float* as2 = (const float*)d_in[15];
    const float* ad2 = (const float*)d_in[16];
    const float* b2  = (const float*)d_in[17];
    float* out = (float*)d_out;

    int E = in_sizes[1] / 2;
    int Etot = E + NN;

    __half* hp;   cudaGetSymbolAddress((void**)&hp, g_hp);
    float* actA;  cudaGetSymbolAddress((void**)&actA, g_actA);
    float* actB;  cudaGetSymbolAddress((void**)&actB, g_actB);
    int* degp;    cudaGetSymbolAddress((void**)&degp, g_deg);

    int gemm_grid = (NN + 127) / 128;
    int wpn_grid = (NN + 7) / 8;

    // ---- fork: CSR build on s2, GEMM0 on main stream, join before aggregate0
    cudaEventRecord(g_hx.fork, 0);
    cudaStreamWaitEvent(g_hx.s2, g_hx.fork, 0);

    cudaMemsetAsync(degp, 0, NN * sizeof(int), g_hx.s2);
    k_probe<<<1, 32, 0, g_hx.s2>>>((const int*)ei);
    k_hist<<<(Etot + 255) / 256, 256, 0, g_hx.s2>>>(ei, E, Etot);
    k_scan_a<<<NBLK, 1024, 0, g_hx.s2>>>();
    k_scan_c<<<(NN + 255) / 256, 256, 0, g_hx.s2>>>();
    k_scatter<<<(Etot + 255) / 256, 256, 0, g_hx.s2>>>(ei, E, Etot);
    cudaEventRecord(g_hx.join, g_hx.s2);

    // GEMM0 (main stream, overlaps CSR build)
    k_gemm128<<<gemm_grid, 256>>>(x, W0, as0, ad0, hp, NN);

    cudaStreamWaitEvent(0, g_hx.join, 0);

    // ---- layer 0 aggregate ----
    k_aggregate128<<<wpn_grid, 256>>>(b0, g0, be0, actA, NN);

    // ---- layer 1 ----
    k_gemm128<<<gemm_grid, 256>>>(actA, W1, as1, ad1, hp, NN);
    k_aggregate128<<<wpn_grid, 256>>>(b1, g1, be1, actB, NN);

    // ---- layer 2 ----
    k_layer2_gemm_dots<<<wpn_grid, 256>>>(actB, W2, as2, ad2, NN);
    k_aggregate10<<<wpn_grid, 256>>>(b2, out, NN);
}

// round 14
// speedup vs baseline: 1.0923x; 1.0097x over previous
#include <cuda_runtime.h>
#include <cuda_bf16.h>
#include <cuda_fp16.h>
#include <stdint.h>
#include <math.h>

typedef unsigned int u32;

#define NN 50000
#define EMAX 600000
#define ETOT_MAX (EMAX + NN)
#define NBLK ((NN + 1023) / 1024)   // 49

// ---------------- scratch (device globals; no allocations allowed) ----------
__device__ __half g_hp[(size_t)NN * 128];    // fp16 messages
__device__ __half g_actA[(size_t)NN * 128];  // fp16 activations
__device__ __half g_actB[(size_t)NN * 128];
__device__ float g_hp2[NN * 10];
__device__ float g_as[NN * 4];
__device__ float g_ad[NN * 4];
__device__ float g_as2[NN];
__device__ float g_ad2[NN];
__device__ int   g_deg[NN];
__device__ int   g_off[NN + 1];
__device__ int   g_cur[NN];
__device__ int   g_csr[ETOT_MAX];
__device__ int   g_bsum[NBLK];
__device__ int   g_is64;
// pre-split weights (bf16 hi/lo), 128x128 each
__device__ __nv_bfloat16 g_W0h[16384], g_W0l[16384];
__device__ __nv_bfloat16 g_W1h[16384], g_W1l[16384];

// host-side stream/event resources, created once at program init.
struct HxStreams {
    cudaStream_t s2;
    cudaEvent_t fork, join;
    HxStreams() {
        cudaStreamCreateWithFlags(&s2, cudaStreamNonBlocking);
        cudaEventCreateWithFlags(&fork, cudaEventDisableTiming);
        cudaEventCreateWithFlags(&join, cudaEventDisableTiming);
    }
};
static HxStreams g_hx;

// ---------------- W pre-split: fp32 -> bf16 hi + bf16 lo ---------------------
__global__ void k_splitW(const float* __restrict__ W,
                         __nv_bfloat16* __restrict__ Wh, __nv_bfloat16* __restrict__ Wl) {
    int i = blockIdx.x * blockDim.x + threadIdx.x;
    if (i >= 16384) return;
    float v = W[i];
    __nv_bfloat16 h = __float2bfloat16(v);
    Wh[i] = h;
    Wl[i] = __float2bfloat16(v - __bfloat162float(h));
}

// ---------------- edge-index dtype probe --------------------------------------
__global__ void k_probe(const int* __restrict__ ei32) {
    if (threadIdx.x == 0) {
        int ok = 1;
        for (int e = 0; e < 64; e++)
            if (ei32[2 * e + 1] != 0) { ok = 0; break; }
        g_is64 = ok;
    }
}

__device__ __forceinline__ int load_idx(const void* ei, long long pos) {
    if (g_is64) return (int)((const long long*)ei)[pos];
    return ((const int*)ei)[pos];
}

// ---------------- CSR build --------------------------------------------------
__global__ void k_hist(const void* __restrict__ ei, int E, int Etot) {
    int e = blockIdx.x * blockDim.x + threadIdx.x;
    if (e >= Etot) return;
    int d = (e < E) ? load_idx(ei, (long long)E + e) : (e - E);
    atomicAdd(&g_deg[d], 1);
}

__global__ void k_scan_a() {
    __shared__ int sh[1024];
    int b = blockIdx.x, t = threadIdx.x;
    int i = b * 1024 + t;
    int v = (i < NN) ? g_deg[i] : 0;
    sh[t] = v;
    __syncthreads();
    for (int off = 1; off < 1024; off <<= 1) {
        int u = (t >= off) ? sh[t - off] : 0;
        __syncthreads();
        sh[t] += u;
        __syncthreads();
    }
    if (i < NN) g_off[i] = sh[t] - v;
    if (t == 1023) g_bsum[b] = sh[t];
}

__global__ void k_scan_c() {
    __shared__ int pre[NBLK];
    if (threadIdx.x == 0) {
        int run = 0;
        for (int b = 0; b < NBLK; b++) { pre[b] = run; run += g_bsum[b]; }
        if (blockIdx.x == 0) g_off[NN] = run;
    }
    __syncthreads();
    int i = blockIdx.x * blockDim.x + threadIdx.x;
    if (i >= NN) return;
    int o = g_off[i] + pre[i >> 10];
    g_off[i] = o;
    g_cur[i] = o;
}

__global__ void k_scatter(const void* __restrict__ ei, int E, int Etot) {
    int e = blockIdx.x * blockDim.x + threadIdx.x;
    if (e >= Etot) return;
    int s, d;
    if (e < E) {
        s = load_idx(ei, e);
        d = load_idx(ei, (long long)E + e);
    } else {
        s = d = e - E;
    }
    int pos = atomicAdd(&g_cur[d], 1);
    g_csr[pos] = s;
}

// ---------------- tensor-core GEMM helpers -----------------------------------
__device__ __forceinline__ u32 s2u(const void* p) {
    return (u32)__cvta_generic_to_shared(p);
}
__device__ __forceinline__ void ldsm4(u32& r0, u32& r1, u32& r2, u32& r3, u32 addr) {
    asm volatile("ldmatrix.sync.aligned.m8n8.x4.shared.b16 {%0,%1,%2,%3}, [%4];"
                 : "=r"(r0), "=r"(r1), "=r"(r2), "=r"(r3) : "r"(addr));
}
__device__ __forceinline__ void ldsm4t(u32& r0, u32& r1, u32& r2, u32& r3, u32 addr) {
    asm volatile("ldmatrix.sync.aligned.m8n8.x4.trans.shared.b16 {%0,%1,%2,%3}, [%4];"
                 : "=r"(r0), "=r"(r1), "=r"(r2), "=r"(r3) : "r"(addr));
}
__device__ __forceinline__ void mma16816(float* c, const u32* a, u32 b0, u32 b1) {
    asm volatile(
        "mma.sync.aligned.m16n8k16.row.col.f32.bf16.bf16.f32 "
        "{%0,%1,%2,%3}, {%4,%5,%6,%7}, {%8,%9}, {%0,%1,%2,%3};"
        : "+f"(c[0]), "+f"(c[1]), "+f"(c[2]), "+f"(c[3])
        : "r"(a[0]), "r"(a[1]), "r"(a[2]), "r"(a[3]), "r"(b0), "r"(b1));
}
__device__ __forceinline__ void split4(float4 v, __nv_bfloat16* ph, __nv_bfloat16* pl) {
    __nv_bfloat16 h0 = __float2bfloat16(v.x);
    __nv_bfloat16 h1 = __float2bfloat16(v.y);
    __nv_bfloat16 h2 = __float2bfloat16(v.z);
    __nv_bfloat16 h3 = __float2bfloat16(v.w);
    ph[0] = h0; ph[1] = h1; ph[2] = h2; ph[3] = h3;
    pl[0] = __float2bfloat16(v.x - __bfloat162float(h0));
    pl[1] = __float2bfloat16(v.y - __bfloat162float(h1));
    pl[2] = __float2bfloat16(v.z - __bfloat162float(h2));
    pl[3] = __float2bfloat16(v.w - __bfloat162float(h3));
}

// C(fp16)[n,128] = A[n,128] @ W[128,128], bf16x2 split mma + fused attn dots.
// A is fp32 (layer 0) or fp16 (layer 1); W comes pre-split (bf16 hi/lo).
#define APAD 40
#define WPAD 136
template <bool HALF_A>
__global__ void __launch_bounds__(256, 2)
k_gemm128(const void* __restrict__ A,
          const __nv_bfloat16* __restrict__ Wh_g, const __nv_bfloat16* __restrict__ Wl_g,
          const float* __restrict__ att_s, const float* __restrict__ att_d,
          __half* __restrict__ C, int n) {
    __shared__ __align__(16) __nv_bfloat16 Ah[128][APAD];
    __shared__ __align__(16) __nv_bfloat16 Al[128][APAD];
    __shared__ __align__(16) __nv_bfloat16 Wh[32][WPAD];
    __shared__ __align__(16) __nv_bfloat16 Wl[32][WPAD];

    int tid = threadIdx.x;
    int lane = tid & 31;
    int wid = tid >> 5;
    int warp_m = wid >> 1;
    int warp_n = wid & 1;
    int row0 = blockIdx.x * 128;
    int wrow0 = warp_m * 32;
    int wcol0 = warp_n * 64;

    int a_r = tid >> 3;
    int a_c = (tid & 7) * 4;
    int w_k = tid >> 3;
    int w_cbase = (tid & 7) * 4;

    float acc[2][8][4];
#pragma unroll
    for (int i = 0; i < 2; i++)
#pragma unroll
        for (int j = 0; j < 8; j++)
#pragma unroll
            for (int q = 0; q < 4; q++) acc[i][j][q] = 0.f;

    float4 pa[4];
    uint2 pwh[4], pwl[4];
#pragma unroll
    for (int it = 0; it < 4; it++) {
        int grow = row0 + a_r + it * 32;
        pa[it] = make_float4(0.f, 0.f, 0.f, 0.f);
        if (grow < n) {
            if (HALF_A) {
                const __half2* p = (const __half2*)((const __half*)A + (size_t)grow * 128 + a_c);
                float2 f01 = __half22float2(p[0]);
                float2 f23 = __half22float2(p[1]);
                pa[it] = make_float4(f01.x, f01.y, f23.x, f23.y);
            } else {
                pa[it] = *(const float4*)((const float*)A + (size_t)grow * 128 + a_c);
            }
        }
        pwh[it] = *(const uint2*)(Wh_g + (size_t)w_k * 128 + w_cbase + it * 32);
        pwl[it] = *(const uint2*)(Wl_g + (size_t)w_k * 128 + w_cbase + it * 32);
    }

    for (int k0 = 0; k0 < 128; k0 += 32) {
#pragma unroll
        for (int it = 0; it < 4; it++) {
            int r = a_r + it * 32;
            split4(pa[it], &Ah[r][a_c], &Al[r][a_c]);
            int c = w_cbase + it * 32;
            *(uint2*)&Wh[w_k][c] = pwh[it];
            *(uint2*)&Wl[w_k][c] = pwl[it];
        }
        __syncthreads();

        if (k0 + 32 < 128) {
#pragma unroll
            for (int it = 0; it < 4; it++) {
                int grow = row0 + a_r + it * 32;
                pa[it] = make_float4(0.f, 0.f, 0.f, 0.f);
                if (grow < n) {
                    if (HALF_A) {
                        const __half2* p = (const __half2*)((const __half*)A + (size_t)grow * 128 + k0 + 32 + a_c);
                        float2 f01 = __half22float2(p[0]);
                        float2 f23 = __half22float2(p[1]);
                        pa[it] = make_float4(f01.x, f01.y, f23.x, f23.y);
                    } else {
                        pa[it] = *(const float4*)((const float*)A + (size_t)grow * 128 + k0 + 32 + a_c);
                    }
                }
                pwh[it] = *(const uint2*)(Wh_g + (size_t)(k0 + 32 + w_k) * 128 + w_cbase + it * 32);
                pwl[it] = *(const uint2*)(Wl_g + (size_t)(k0 + 32 + w_k) * 128 + w_cbase + it * 32);
            }
        }

#pragma unroll
        for (int ks = 0; ks < 32; ks += 16) {
            u32 ah[2][4], al[2][4], bb[4][4];
            int arow = (lane & 15);
            int acol = ks + ((lane >> 4) << 3);
#pragma unroll
            for (int mt = 0; mt < 2; mt++)
                ldsm4(ah[mt][0], ah[mt][1], ah[mt][2], ah[mt][3],
                      s2u(&Ah[wrow0 + mt * 16 + arow][acol]));
#pragma unroll
            for (int p = 0; p < 4; p++) {
                int j = p * 2 + (lane >> 4);
                ldsm4t(bb[p][0], bb[p][1], bb[p][2], bb[p][3],
                       s2u(&Wh[ks + (lane & 15)][wcol0 + j * 8]));
            }
#pragma unroll
            for (int mt = 0; mt < 2; mt++)
#pragma unroll
                for (int j = 0; j < 8; j++)
                    mma16816(acc[mt][j], ah[mt], bb[j >> 1][(j & 1) * 2], bb[j >> 1][(j & 1) * 2 + 1]);
#pragma unroll
            for (int mt = 0; mt < 2; mt++)
                ldsm4(al[mt][0], al[mt][1], al[mt][2], al[mt][3],
                      s2u(&Al[wrow0 + mt * 16 + arow][acol]));
#pragma unroll
            for (int mt = 0; mt < 2; mt++)
#pragma unroll
                for (int j = 0; j < 8; j++)
                    mma16816(acc[mt][j], al[mt], bb[j >> 1][(j & 1) * 2], bb[j >> 1][(j & 1) * 2 + 1]);
#pragma unroll
            for (int p = 0; p < 4; p++) {
                int j = p * 2 + (lane >> 4);
                ldsm4t(bb[p][0], bb[p][1], bb[p][2], bb[p][3],
                       s2u(&Wl[ks + (lane & 15)][wcol0 + j * 8]));
            }
#pragma unroll
            for (int mt = 0; mt < 2; mt++)
#pragma unroll
                for (int j = 0; j < 8; j++)
                    mma16816(acc[mt][j], ah[mt], bb[j >> 1][(j & 1) * 2], bb[j >> 1][(j & 1) * 2 + 1]);
        }
        __syncthreads();
    }

    float2 vs[8], vd[8];
#pragma unroll
    for (int j = 0; j < 8; j++) {
        int col = wcol0 + j * 8 + (lane & 3) * 2;
        vs[j] = *(const float2*)(att_s + col);
        vd[j] = *(const float2*)(att_d + col);
    }

#pragma unroll
    for (int mt = 0; mt < 2; mt++) {
        int r0 = row0 + wrow0 + mt * 16 + (lane >> 2);
        int r1 = r0 + 8;
        float ps0[2] = {0.f, 0.f}, ps1[2] = {0.f, 0.f};
        float pd0[2] = {0.f, 0.f}, pd1[2] = {0.f, 0.f};
#pragma unroll
        for (int j = 0; j < 8; j++) {
            int cofs = wcol0 + j * 8 + (lane & 3) * 2;
            if (r0 < n)
                *(__half2*)(C + (size_t)r0 * 128 + cofs) =
                    __floats2half2_rn(acc[mt][j][0], acc[mt][j][1]);
            if (r1 < n)
                *(__half2*)(C + (size_t)r1 * 128 + cofs) =
                    __floats2half2_rn(acc[mt][j][2], acc[mt][j][3]);
            int h = j >> 2;
            ps0[h] += acc[mt][j][0] * vs[j].x + acc[mt][j][1] * vs[j].y;
            ps1[h] += acc[mt][j][2] * vs[j].x + acc[mt][j][3] * vs[j].y;
            pd0[h] += acc[mt][j][0] * vd[j].x + acc[mt][j][1] * vd[j].y;
            pd1[h] += acc[mt][j][2] * vd[j].x + acc[mt][j][3] * vd[j].y;
        }
#pragma unroll
        for (int o = 1; o <= 2; o <<= 1) {
#pragma unroll
            for (int h = 0; h < 2; h++) {
                ps0[h] += __shfl_xor_sync(0xffffffffu, ps0[h], o);
                ps1[h] += __shfl_xor_sync(0xffffffffu, ps1[h], o);
                pd0[h] += __shfl_xor_sync(0xffffffffu, pd0[h], o);
                pd1[h] += __shfl_xor_sync(0xffffffffu, pd1[h], o);
            }
        }
        if ((lane & 3) == 0) {
#pragma unroll
            for (int h = 0; h < 2; h++) {
                int hd = warp_n * 2 + h;
                if (r0 < n) { g_as[r0 * 4 + hd] = ps0[h]; g_ad[r0 * 4 + hd] = pd0[h]; }
                if (r1 < n) { g_as[r1 * 4 + hd] = ps1[h]; g_ad[r1 * 4 + hd] = pd1[h]; }
            }
        }
    }
}

__device__ __forceinline__ float leaky(float x) { return x > 0.f ? x : 0.2f * x; }

// ---------------- single-pass segment softmax + aggregate + bias/BN/ELU ------
#define CHUNK 64
__global__ void k_aggregate128(const float* __restrict__ bias, const float* __restrict__ gamma,
                               const float* __restrict__ beta, __half* __restrict__ out, int n) {
    __shared__ float4 s_wv[8][CHUNK];
    __shared__ int    s_idx[8][CHUNK];
    int gt = blockIdx.x * blockDim.x + threadIdx.x;
    int node = gt >> 5;
    if (node >= n) return;
    int lane = threadIdx.x & 31;
    int wrp = (threadIdx.x >> 5);
    int s0 = g_off[node], s1 = g_off[node + 1];

    float ad0 = g_ad[node * 4 + 0], ad1 = g_ad[node * 4 + 1];
    float ad2 = g_ad[node * 4 + 2], ad3 = g_ad[node * 4 + 3];

    int hl = lane >> 3;
    float dl0 = 0.f, dl1 = 0.f, dl2 = 0.f, dl3 = 0.f;
    float ax = 0.f, ay = 0.f, az = 0.f, aw = 0.f;

    for (int c0 = s0; c0 < s1; c0 += CHUNK) {
        int cnt = min(CHUNK, s1 - c0);
        for (int i = lane; i < cnt; i += 32) {
            int s = g_csr[c0 + i];
            float4 av = *(const float4*)(g_as + s * 4);
            float4 wv;
            wv.x = __expf(leaky(av.x + ad0));
            wv.y = __expf(leaky(av.y + ad1));
            wv.z = __expf(leaky(av.z + ad2));
            wv.w = __expf(leaky(av.w + ad3));
            dl0 += wv.x; dl1 += wv.y; dl2 += wv.z; dl3 += wv.w;
            s_wv[wrp][i] = wv;
            s_idx[wrp][i] = s;
        }
        __syncwarp();
#pragma unroll 4
        for (int j = 0; j < cnt; j++) {
            int s = s_idx[wrp][j];
            float wt = ((const float*)&s_wv[wrp][j])[hl];
            const __half2* p = (const __half2*)(g_hp + (size_t)s * 128 + lane * 4);
            float2 v01 = __half22float2(p[0]);
            float2 v23 = __half22float2(p[1]);
            ax += v01.x * wt; ay += v01.y * wt; az += v23.x * wt; aw += v23.y * wt;
        }
        __syncwarp();
    }

#pragma unroll
    for (int o = 16; o > 0; o >>= 1) {
        dl0 += __shfl_xor_sync(0xffffffffu, dl0, o);
        dl1 += __shfl_xor_sync(0xffffffffu, dl1, o);
        dl2 += __shfl_xor_sync(0xffffffffu, dl2, o);
        dl3 += __shfl_xor_sync(0xffffffffu, dl3, o);
    }
    float dh = (hl == 0) ? dl0 : (hl == 1) ? dl1 : (hl == 2) ? dl2 : dl3;
    float inv = 1.f / (dh + 1e-16f);

    const float invsq = rsqrtf(1.0f + 1e-5f);
    float res[4] = {ax * inv, ay * inv, az * inv, aw * inv};
#pragma unroll
    for (int j = 0; j < 4; j++) {
        int c = lane * 4 + j;
        float v = res[j] + bias[c];
        v = v * (gamma[c] * invsq) + beta[c];
        res[j] = (v > 0.f) ? v : expm1f(v);
    }
    __half2* po = (__half2*)(out + (size_t)node * 128 + lane * 4);
    po[0] = __floats2half2_rn(res[0], res[1]);
    po[1] = __floats2half2_rn(res[2], res[3]);
}

// ---------------- layer 2: GEMM [N,128]@[128,10] fused with attn dots --------
__global__ void k_layer2_gemm_dots(const __half* __restrict__ act, const float* __restrict__ W2,
                                   const float* __restrict__ as2, const float* __restrict__ ad2,
                                   int n) {
    __shared__ float W2t[10 * 128];
    __shared__ float s_as[10], s_ad[10];
    int tid = threadIdx.x;
    for (int i = tid; i < 1280; i += 256) {
        int k = i / 10, c = i % 10;
        W2t[c * 128 + k] = W2[i];
    }
    if (tid < 10) { s_as[tid] = as2[tid]; s_ad[tid] = ad2[tid]; }
    __syncthreads();

    int node = (blockIdx.x * blockDim.x + tid) >> 5;
    if (node >= n) return;
    int lane = tid & 31;
    const __half2* pv = (const __half2*)(act + (size_t)node * 128 + lane * 4);
    float2 f01 = __half22float2(pv[0]);
    float2 f23 = __half22float2(pv[1]);
    float4 v = make_float4(f01.x, f01.y, f23.x, f23.y);
    float as_acc = 0.f, ad_acc = 0.f;
#pragma unroll
    for (int c = 0; c < 10; c++) {
        const float* wc = W2t + c * 128 + lane * 4;
        float p = v.x * wc[0] + v.y * wc[1] + v.z * wc[2] + v.w * wc[3];
#pragma unroll
        for (int o = 16; o > 0; o >>= 1) p += __shfl_xor_sync(0xffffffffu, p, o);
        if (lane == 0) g_hp2[node * 10 + c] = p;
        as_acc += p * s_as[c];
        ad_acc += p * s_ad[c];
    }
    if (lane == 0) { g_as2[node] = as_acc; g_ad2[node] = ad_acc; }
}

// single-pass edge-parallel aggregate for CLS layer
__global__ void k_aggregate10(const float* __restrict__ b2, float* __restrict__ out, int n) {
    int gt = blockIdx.x * blockDim.x + threadIdx.x;
    int node = gt >> 5;
    if (node >= n) return;
    int lane = threadIdx.x & 31;
    int s0 = g_off[node], s1 = g_off[node + 1];
    float adn = g_ad2[node];

    float dsum = 0.f;
    float acc[10];
#pragma unroll
    for (int c = 0; c < 10; c++) acc[c] = 0.f;
    for (int i = s0 + lane; i < s1; i += 32) {
        int s = g_csr[i];
        float w = __expf(leaky(g_as2[s] + adn));
        dsum += w;
        const float2* p = (const float2*)(g_hp2 + s * 10);
#pragma unroll
        for (int c = 0; c < 5; c++) {
            float2 v = p[c];
            acc[2 * c]     += v.x * w;
            acc[2 * c + 1] += v.y * w;
        }
    }
#pragma unroll
    for (int o = 16; o > 0; o >>= 1) {
        dsum += __shfl_xor_sync(0xffffffffu, dsum, o);
#pragma unroll
        for (int c = 0; c < 10; c++)
            acc[c] += __shfl_xor_sync(0xffffffffu, acc[c], o);
    }
    float inv = 1.f / (dsum + 1e-16f);
    if (lane < 10) out[node * 10 + lane] = acc[lane] * inv + b2[lane];
}

// ---------------- launch -----------------------------------------------------
extern "C" void kernel_launch(void* const* d_in, const int* in_sizes, int n_in,
                              void* d_out, int out_size) {
    const float* x   = (const float*)d_in[0];
    const void*  ei  = d_in[1];
    const float* W0  = (const float*)d_in[2];
    const float* as0 = (const float*)d_in[3];
    const float* ad0 = (const float*)d_in[4];
    const float* b0  = (const float*)d_in[5];
    const float* g0  = (const float*)d_in[6];
    const float* be0 = (const float*)d_in[7];
    const float* W1  = (const float*)d_in[8];
    const float* as1 = (const float*)d_in[9];
    const float* ad1 = (const float*)d_in[10];
    const float* b1  = (const float*)d_in[11];
    const float* g1  = (const float*)d_in[12];
    const float* be1 = (const float*)d_in[13];
    const float* W2  = (const float*)d_in[14];
    const float* as2 = (const float*)d_in[15];
    const float* ad2 = (const float*)d_in[16];
    const float* b2  = (const float*)d_in[17];
    float* out = (float*)d_out;

    int E = in_sizes[1] / 2;
    int Etot = E + NN;

    __half* hp;   cudaGetSymbolAddress((void**)&hp, g_hp);
    __half* actA; cudaGetSymbolAddress((void**)&actA, g_actA);
    __half* actB; cudaGetSymbolAddress((void**)&actB, g_actB);
    int* degp;    cudaGetSymbolAddress((void**)&degp, g_deg);
    __nv_bfloat16 *w0h, *w0l, *w1h, *w1l;
    cudaGetSymbolAddress((void**)&w0h, g_W0h);
    cudaGetSymbolAddress((void**)&w0l, g_W0l);
    cudaGetSymbolAddress((void**)&w1h, g_W1h);
    cudaGetSymbolAddress((void**)&w1l, g_W1l);

    int gemm_grid = (NN + 127) / 128;
    int wpn_grid = (NN + 7) / 8;

    // ---- fork: CSR build + W1 split on s2; W0 split + GEMM0 on main stream
    cudaEventRecord(g_hx.fork, 0);
    cudaStreamWaitEvent(g_hx.s2, g_hx.fork, 0);

    k_splitW<<<64, 256, 0, g_hx.s2>>>(W1, w1h, w1l);
    cudaMemsetAsync(degp, 0, NN * sizeof(int), g_hx.s2);
    k_probe<<<1, 32, 0, g_hx.s2>>>((const int*)ei);
    k_hist<<<(Etot + 255) / 256, 256, 0, g_hx.s2>>>(ei, E, Etot);
    k_scan_a<<<NBLK, 1024, 0, g_hx.s2>>>();
    k_scan_c<<<(NN + 255) / 256, 256, 0, g_hx.s2>>>();
    k_scatter<<<(Etot + 255) / 256, 256, 0, g_hx.s2>>>(ei, E, Etot);
    cudaEventRecord(g_hx.join, g_hx.s2);

    k_splitW<<<64, 256>>>(W0, w0h, w0l);
    k_gemm128<false><<<gemm_grid, 256>>>(x, w0h, w0l, as0, ad0, hp, NN);

    cudaStreamWaitEvent(0, g_hx.join, 0);

    // ---- layer 0 aggregate ----
    k_aggregate128<<<wpn_grid, 256>>>(b0, g0, be0, actA, NN);

    // ---- layer 1 ----
    k_gemm128<true><<<gemm_grid, 256>>>(actA, w1h, w1l, as1, ad1, hp, NN);
    k_aggregate128<<<wpn_grid, 256>>>(b1, g1, be1, actB, NN);

    // ---- layer 2 ----
    k_layer2_gemm_dots<<<wpn_grid, 256>>>(actB, W2, as2, ad2, NN);
    k_aggregate10<<<wpn_grid, 256>>>(b2, out, NN);
}

// round 15
// speedup vs baseline: 1.1222x; 1.0273x over previous
#include <cuda_runtime.h>
#include <cuda_bf16.h>
#include <cuda_fp16.h>
#include <stdint.h>
#include <math.h>

typedef unsigned int u32;

#define NN 50000
#define EMAX 600000
#define ETOT_MAX (EMAX + NN)
#define NBLK ((NN + 1023) / 1024)   // 49

// ---------------- scratch (device globals; no allocations allowed) ----------
__device__ __half g_hp[(size_t)NN * 128];    // fp16 messages
__device__ __half g_actA[(size_t)NN * 128];  // fp16 activations
__device__ __half g_actB[(size_t)NN * 128];
__device__ float g_hp2[NN * 10];
__device__ float g_as[NN * 4];
__device__ float g_ad[NN * 4];
__device__ float g_as2[NN];
__device__ float g_ad2[NN];
__device__ int   g_deg[NN];
__device__ int   g_off[NN + 1];
__device__ int   g_cur[NN];
__device__ int   g_csr[ETOT_MAX];
__device__ int   g_bsum[NBLK];
__device__ int   g_is64;
// pre-split weights (fp16 hi/lo), 128x128 each
__device__ __half g_W0h[16384], g_W0l[16384];
__device__ __half g_W1h[16384], g_W1l[16384];

// host-side stream/event resources, created once at program init.
struct HxStreams {
    cudaStream_t s2;
    cudaEvent_t fork, join;
    HxStreams() {
        cudaStreamCreateWithFlags(&s2, cudaStreamNonBlocking);
        cudaEventCreateWithFlags(&fork, cudaEventDisableTiming);
        cudaEventCreateWithFlags(&join, cudaEventDisableTiming);
    }
};
static HxStreams g_hx;

// ---------------- W pre-split: fp32 -> fp16 hi + fp16 lo ---------------------
__global__ void k_splitW(const float* __restrict__ W,
                         __half* __restrict__ Wh, __half* __restrict__ Wl) {
    int i = blockIdx.x * blockDim.x + threadIdx.x;
    if (i >= 16384) return;
    float v = W[i];
    __half h = __float2half_rn(v);
    Wh[i] = h;
    Wl[i] = __float2half_rn(v - __half2float(h));
}

// ---------------- edge-index dtype probe --------------------------------------
__global__ void k_probe(const int* __restrict__ ei32) {
    if (threadIdx.x == 0) {
        int ok = 1;
        for (int e = 0; e < 64; e++)
            if (ei32[2 * e + 1] != 0) { ok = 0; break; }
        g_is64 = ok;
    }
}

__device__ __forceinline__ int load_idx(const void* ei, long long pos) {
    if (g_is64) return (int)((const long long*)ei)[pos];
    return ((const int*)ei)[pos];
}

// ---------------- CSR build --------------------------------------------------
__global__ void k_hist(const void* __restrict__ ei, int E, int Etot) {
    int e = blockIdx.x * blockDim.x + threadIdx.x;
    if (e >= Etot) return;
    int d = (e < E) ? load_idx(ei, (long long)E + e) : (e - E);
    atomicAdd(&g_deg[d], 1);
}

__global__ void k_scan_a() {
    __shared__ int sh[1024];
    int b = blockIdx.x, t = threadIdx.x;
    int i = b * 1024 + t;
    int v = (i < NN) ? g_deg[i] : 0;
    sh[t] = v;
    __syncthreads();
    for (int off = 1; off < 1024; off <<= 1) {
        int u = (t >= off) ? sh[t - off] : 0;
        __syncthreads();
        sh[t] += u;
        __syncthreads();
    }
    if (i < NN) g_off[i] = sh[t] - v;
    if (t == 1023) g_bsum[b] = sh[t];
}

__global__ void k_scan_c() {
    __shared__ int pre[NBLK];
    if (threadIdx.x == 0) {
        int run = 0;
        for (int b = 0; b < NBLK; b++) { pre[b] = run; run += g_bsum[b]; }
        if (blockIdx.x == 0) g_off[NN] = run;
    }
    __syncthreads();
    int i = blockIdx.x * blockDim.x + threadIdx.x;
    if (i >= NN) return;
    int o = g_off[i] + pre[i >> 10];
    g_off[i] = o;
    g_cur[i] = o;
}

__global__ void k_scatter(const void* __restrict__ ei, int E, int Etot) {
    int e = blockIdx.x * blockDim.x + threadIdx.x;
    if (e >= Etot) return;
    int s, d;
    if (e < E) {
        s = load_idx(ei, e);
        d = load_idx(ei, (long long)E + e);
    } else {
        s = d = e - E;
    }
    int pos = atomicAdd(&g_cur[d], 1);
    g_csr[pos] = s;
}

// ---------------- tensor-core GEMM helpers -----------------------------------
__device__ __forceinline__ u32 s2u(const void* p) {
    return (u32)__cvta_generic_to_shared(p);
}
__device__ __forceinline__ void ldsm4(u32& r0, u32& r1, u32& r2, u32& r3, u32 addr) {
    asm volatile("ldmatrix.sync.aligned.m8n8.x4.shared.b16 {%0,%1,%2,%3}, [%4];"
                 : "=r"(r0), "=r"(r1), "=r"(r2), "=r"(r3) : "r"(addr));
}
__device__ __forceinline__ void ldsm4t(u32& r0, u32& r1, u32& r2, u32& r3, u32 addr) {
    asm volatile("ldmatrix.sync.aligned.m8n8.x4.trans.shared.b16 {%0,%1,%2,%3}, [%4];"
                 : "=r"(r0), "=r"(r1), "=r"(r2), "=r"(r3) : "r"(addr));
}
__device__ __forceinline__ void mma16816h(float* c, const u32* a, u32 b0, u32 b1) {
    asm volatile(
        "mma.sync.aligned.m16n8k16.row.col.f32.f16.f16.f32 "
        "{%0,%1,%2,%3}, {%4,%5,%6,%7}, {%8,%9}, {%0,%1,%2,%3};"
        : "+f"(c[0]), "+f"(c[1]), "+f"(c[2]), "+f"(c[3])
        : "r"(a[0]), "r"(a[1]), "r"(a[2]), "r"(a[3]), "r"(b0), "r"(b1));
}

// C(fp16)[n,128] = A[n,128] @ W[128,128], fp16 mma with W split (hi+lo), fp32 acc.
// A: fp32 (layer 0, rounded to fp16) or fp16 (layer 1, exact). Fused attn dots.
#define APAD 40
#define WPAD 136
template <bool HALF_A>
__global__ void __launch_bounds__(256, 2)
k_gemm128(const void* __restrict__ A,
          const __half* __restrict__ Wh_g, const __half* __restrict__ Wl_g,
          const float* __restrict__ att_s, const float* __restrict__ att_d,
          __half* __restrict__ C, int n) {
    __shared__ __align__(16) __half As[128][APAD];
    __shared__ __align__(16) __half Wh[32][WPAD];
    __shared__ __align__(16) __half Wl[32][WPAD];

    int tid = threadIdx.x;
    int lane = tid & 31;
    int wid = tid >> 5;
    int warp_m = wid >> 1;
    int warp_n = wid & 1;
    int row0 = blockIdx.x * 128;
    int wrow0 = warp_m * 32;
    int wcol0 = warp_n * 64;

    int a_r = tid >> 3;
    int a_c = (tid & 7) * 4;
    int w_k = tid >> 3;
    int w_cbase = (tid & 7) * 4;

    float acc[2][8][4];
#pragma unroll
    for (int i = 0; i < 2; i++)
#pragma unroll
        for (int j = 0; j < 8; j++)
#pragma unroll
            for (int q = 0; q < 4; q++) acc[i][j][q] = 0.f;

    float4 pa[4];
    uint2 paw[4], pwh[4], pwl[4];
#pragma unroll
    for (int it = 0; it < 4; it++) {
        int grow = row0 + a_r + it * 32;
        if (HALF_A) {
            paw[it] = make_uint2(0u, 0u);
            if (grow < n) paw[it] = *(const uint2*)((const __half*)A + (size_t)grow * 128 + a_c);
        } else {
            pa[it] = make_float4(0.f, 0.f, 0.f, 0.f);
            if (grow < n) pa[it] = *(const float4*)((const float*)A + (size_t)grow * 128 + a_c);
        }
        pwh[it] = *(const uint2*)(Wh_g + (size_t)w_k * 128 + w_cbase + it * 32);
        pwl[it] = *(const uint2*)(Wl_g + (size_t)w_k * 128 + w_cbase + it * 32);
    }

    for (int k0 = 0; k0 < 128; k0 += 32) {
#pragma unroll
        for (int it = 0; it < 4; it++) {
            int r = a_r + it * 32;
            if (HALF_A) {
                *(uint2*)&As[r][a_c] = paw[it];
            } else {
                __half2 h01 = __floats2half2_rn(pa[it].x, pa[it].y);
                __half2 h23 = __floats2half2_rn(pa[it].z, pa[it].w);
                *(__half2*)&As[r][a_c] = h01;
                *(__half2*)&As[r][a_c + 2] = h23;
            }
            int c = w_cbase + it * 32;
            *(uint2*)&Wh[w_k][c] = pwh[it];
            *(uint2*)&Wl[w_k][c] = pwl[it];
        }
        __syncthreads();

        if (k0 + 32 < 128) {
#pragma unroll
            for (int it = 0; it < 4; it++) {
                int grow = row0 + a_r + it * 32;
                if (HALF_A) {
                    paw[it] = make_uint2(0u, 0u);
                    if (grow < n)
                        paw[it] = *(const uint2*)((const __half*)A + (size_t)grow * 128 + k0 + 32 + a_c);
                } else {
                    pa[it] = make_float4(0.f, 0.f, 0.f, 0.f);
                    if (grow < n)
                        pa[it] = *(const float4*)((const float*)A + (size_t)grow * 128 + k0 + 32 + a_c);
                }
                pwh[it] = *(const uint2*)(Wh_g + (size_t)(k0 + 32 + w_k) * 128 + w_cbase + it * 32);
                pwl[it] = *(const uint2*)(Wl_g + (size_t)(k0 + 32 + w_k) * 128 + w_cbase + it * 32);
            }
        }

#pragma unroll
        for (int ks = 0; ks < 32; ks += 16) {
            u32 aa[2][4], bb[4][4];
            int arow = (lane & 15);
            int acol = ks + ((lane >> 4) << 3);
#pragma unroll
            for (int mt = 0; mt < 2; mt++)
                ldsm4(aa[mt][0], aa[mt][1], aa[mt][2], aa[mt][3],
                      s2u(&As[wrow0 + mt * 16 + arow][acol]));
            // W hi
#pragma unroll
            for (int p = 0; p < 4; p++) {
                int j = p * 2 + (lane >> 4);
                ldsm4t(bb[p][0], bb[p][1], bb[p][2], bb[p][3],
                       s2u(&Wh[ks + (lane & 15)][wcol0 + j * 8]));
            }
#pragma unroll
            for (int mt = 0; mt < 2; mt++)
#pragma unroll
                for (int j = 0; j < 8; j++)
                    mma16816h(acc[mt][j], aa[mt], bb[j >> 1][(j & 1) * 2], bb[j >> 1][(j & 1) * 2 + 1]);
            // W lo
#pragma unroll
            for (int p = 0; p < 4; p++) {
                int j = p * 2 + (lane >> 4);
                ldsm4t(bb[p][0], bb[p][1], bb[p][2], bb[p][3],
                       s2u(&Wl[ks + (lane & 15)][wcol0 + j * 8]));
            }
#pragma unroll
            for (int mt = 0; mt < 2; mt++)
#pragma unroll
                for (int j = 0; j < 8; j++)
                    mma16816h(acc[mt][j], aa[mt], bb[j >> 1][(j & 1) * 2], bb[j >> 1][(j & 1) * 2 + 1]);
        }
        __syncthreads();
    }

    float2 vs[8], vd[8];
#pragma unroll
    for (int j = 0; j < 8; j++) {
        int col = wcol0 + j * 8 + (lane & 3) * 2;
        vs[j] = *(const float2*)(att_s + col);
        vd[j] = *(const float2*)(att_d + col);
    }

#pragma unroll
    for (int mt = 0; mt < 2; mt++) {
        int r0 = row0 + wrow0 + mt * 16 + (lane >> 2);
        int r1 = r0 + 8;
        float ps0[2] = {0.f, 0.f}, ps1[2] = {0.f, 0.f};
        float pd0[2] = {0.f, 0.f}, pd1[2] = {0.f, 0.f};
#pragma unroll
        for (int j = 0; j < 8; j++) {
            int cofs = wcol0 + j * 8 + (lane & 3) * 2;
            if (r0 < n)
                *(__half2*)(C + (size_t)r0 * 128 + cofs) =
                    __floats2half2_rn(acc[mt][j][0], acc[mt][j][1]);
            if (r1 < n)
                *(__half2*)(C + (size_t)r1 * 128 + cofs) =
                    __floats2half2_rn(acc[mt][j][2], acc[mt][j][3]);
            int h = j >> 2;
            ps0[h] += acc[mt][j][0] * vs[j].x + acc[mt][j][1] * vs[j].y;
            ps1[h] += acc[mt][j][2] * vs[j].x + acc[mt][j][3] * vs[j].y;
            pd0[h] += acc[mt][j][0] * vd[j].x + acc[mt][j][1] * vd[j].y;
            pd1[h] += acc[mt][j][2] * vd[j].x + acc[mt][j][3] * vd[j].y;
        }
#pragma unroll
        for (int o = 1; o <= 2; o <<= 1) {
#pragma unroll
            for (int h = 0; h < 2; h++) {
                ps0[h] += __shfl_xor_sync(0xffffffffu, ps0[h], o);
                ps1[h] += __shfl_xor_sync(0xffffffffu, ps1[h], o);
                pd0[h] += __shfl_xor_sync(0xffffffffu, pd0[h], o);
                pd1[h] += __shfl_xor_sync(0xffffffffu, pd1[h], o);
            }
        }
        if ((lane & 3) == 0) {
#pragma unroll
            for (int h = 0; h < 2; h++) {
                int hd = warp_n * 2 + h;
                if (r0 < n) { g_as[r0 * 4 + hd] = ps0[h]; g_ad[r0 * 4 + hd] = pd0[h]; }
                if (r1 < n) { g_as[r1 * 4 + hd] = ps1[h]; g_ad[r1 * 4 + hd] = pd1[h]; }
            }
        }
    }
}

__device__ __forceinline__ float leaky(float x) { return x > 0.f ? x : 0.2f * x; }

// ---------------- single-pass segment softmax + aggregate + bias/BN/ELU ------
#define CHUNK 64
__global__ void k_aggregate128(const float* __restrict__ bias, const float* __restrict__ gamma,
                               const float* __restrict__ beta, __half* __restrict__ out, int n) {
    __shared__ float4 s_wv[8][CHUNK];
    __shared__ int    s_idx[8][CHUNK];
    int gt = blockIdx.x * blockDim.x + threadIdx.x;
    int node = gt >> 5;
    if (node >= n) return;
    int lane = threadIdx.x & 31;
    int wrp = (threadIdx.x >> 5);
    int s0 = g_off[node], s1 = g_off[node + 1];

    float ad0 = g_ad[node * 4 + 0], ad1 = g_ad[node * 4 + 1];
    float ad2 = g_ad[node * 4 + 2], ad3 = g_ad[node * 4 + 3];

    int hl = lane >> 3;
    float dl0 = 0.f, dl1 = 0.f, dl2 = 0.f, dl3 = 0.f;
    float ax = 0.f, ay = 0.f, az = 0.f, aw = 0.f;

    for (int c0 = s0; c0 < s1; c0 += CHUNK) {
        int cnt = min(CHUNK, s1 - c0);
        for (int i = lane; i < cnt; i += 32) {
            int s = g_csr[c0 + i];
            float4 av = *(const float4*)(g_as + s * 4);
            float4 wv;
            wv.x = __expf(leaky(av.x + ad0));
            wv.y = __expf(leaky(av.y + ad1));
            wv.z = __expf(leaky(av.z + ad2));
            wv.w = __expf(leaky(av.w + ad3));
            dl0 += wv.x; dl1 += wv.y; dl2 += wv.z; dl3 += wv.w;
            s_wv[wrp][i] = wv;
            s_idx[wrp][i] = s;
        }
        __syncwarp();
#pragma unroll 4
        for (int j = 0; j < cnt; j++) {
            int s = s_idx[wrp][j];
            float wt = ((const float*)&s_wv[wrp][j])[hl];
            const __half2* p = (const __half2*)(g_hp + (size_t)s * 128 + lane * 4);
            float2 v01 = __half22float2(p[0]);
            float2 v23 = __half22float2(p[1]);
            ax += v01.x * wt; ay += v01.y * wt; az += v23.x * wt; aw += v23.y * wt;
        }
        __syncwarp();
    }

#pragma unroll
    for (int o = 16; o > 0; o >>= 1) {
        dl0 += __shfl_xor_sync(0xffffffffu, dl0, o);
        dl1 += __shfl_xor_sync(0xffffffffu, dl1, o);
        dl2 += __shfl_xor_sync(0xffffffffu, dl2, o);
        dl3 += __shfl_xor_sync(0xffffffffu, dl3, o);
    }
    float dh = (hl == 0) ? dl0 : (hl == 1) ? dl1 : (hl == 2) ? dl2 : dl3;
    float inv = 1.f / (dh + 1e-16f);

    const float invsq = rsqrtf(1.0f + 1e-5f);
    float res[4] = {ax * inv, ay * inv, az * inv, aw * inv};
#pragma unroll
    for (int j = 0; j < 4; j++) {
        int c = lane * 4 + j;
        float v = res[j] + bias[c];
        v = v * (gamma[c] * invsq) + beta[c];
        res[j] = (v > 0.f) ? v : expm1f(v);
    }
    __half2* po = (__half2*)(out + (size_t)node * 128 + lane * 4);
    po[0] = __floats2half2_rn(res[0], res[1]);
    po[1] = __floats2half2_rn(res[2], res[3]);
}

// ---------------- layer 2: GEMM [N,128]@[128,10] fused with attn dots --------
__global__ void k_layer2_gemm_dots(const __half* __restrict__ act, const float* __restrict__ W2,
                                   const float* __restrict__ as2, const float* __restrict__ ad2,
                                   int n) {
    __shared__ float W2t[10 * 128];
    __shared__ float s_as[10], s_ad[10];
    int tid = threadIdx.x;
    for (int i = tid; i < 1280; i += 256) {
        int k = i / 10, c = i % 10;
        W2t[c * 128 + k] = W2[i];
    }
    if (tid < 10) { s_as[tid] = as2[tid]; s_ad[tid] = ad2[tid]; }
    __syncthreads();

    int node = (blockIdx.x * blockDim.x + tid) >> 5;
    if (node >= n) return;
    int lane = tid & 31;
    const __half2* pv = (const __half2*)(act + (size_t)node * 128 + lane * 4);
    float2 f01 = __half22float2(pv[0]);
    float2 f23 = __half22float2(pv[1]);
    float4 v = make_float4(f01.x, f01.y, f23.x, f23.y);
    float as_acc = 0.f, ad_acc = 0.f;
#pragma unroll
    for (int c = 0; c < 10; c++) {
        const float* wc = W2t + c * 128 + lane * 4;
        float p = v.x * wc[0] + v.y * wc[1] + v.z * wc[2] + v.w * wc[3];
#pragma unroll
        for (int o = 16; o > 0; o >>= 1) p += __shfl_xor_sync(0xffffffffu, p, o);
        if (lane == 0) g_hp2[node * 10 + c] = p;
        as_acc += p * s_as[c];
        ad_acc += p * s_ad[c];
    }
    if (lane == 0) { g_as2[node] = as_acc; g_ad2[node] = ad_acc; }
}

// single-pass edge-parallel aggregate for CLS layer
__global__ void k_aggregate10(const float* __restrict__ b2, float* __restrict__ out, int n) {
    int gt = blockIdx.x * blockDim.x + threadIdx.x;
    int node = gt >> 5;
    if (node >= n) return;
    int lane = threadIdx.x & 31;
    int s0 = g_off[node], s1 = g_off[node + 1];
    float adn = g_ad2[node];

    float dsum = 0.f;
    float acc[10];
#pragma unroll
    for (int c = 0; c < 10; c++) acc[c] = 0.f;
    for (int i = s0 + lane; i < s1; i += 32) {
        int s = g_csr[i];
        float w = __expf(leaky(g_as2[s] + adn));
        dsum += w;
        const float2* p = (const float2*)(g_hp2 + s * 10);
#pragma unroll
        for (int c = 0; c < 5; c++) {
            float2 v = p[c];
            acc[2 * c]     += v.x * w;
            acc[2 * c + 1] += v.y * w;
        }
    }
#pragma unroll
    for (int o = 16; o > 0; o >>= 1) {
        dsum += __shfl_xor_sync(0xffffffffu, dsum, o);
#pragma unroll
        for (int c = 0; c < 10; c++)
            acc[c] += __shfl_xor_sync(0xffffffffu, acc[c], o);
    }
    float inv = 1.f / (dsum + 1e-16f);
    if (lane < 10) out[node * 10 + lane] = acc[lane] * inv + b2[lane];
}

// ---------------- launch -----------------------------------------------------
extern "C" void kernel_launch(void* const* d_in, const int* in_sizes, int n_in,
                              void* d_out, int out_size) {
    const float* x   = (const float*)d_in[0];
    const void*  ei  = d_in[1];
    const float* W0  = (const float*)d_in[2];
    const float* as0 = (const float*)d_in[3];
    const float* ad0 = (const float*)d_in[4];
    const float* b0  = (const float*)d_in[5];
    const float* g0  = (const float*)d_in[6];
    const float* be0 = (const float*)d_in[7];
    const float* W1  = (const float*)d_in[8];
    const float* as1 = (const float*)d_in[9];
    const float* ad1 = (const float*)d_in[10];
    const float* b1  = (const float*)d_in[11];
    const float* g1  = (const float*)d_in[12];
    const float* be1 = (const float*)d_in[13];
    const float* W2  = (const float*)d_in[14];
    const float* as2 = (const float*)d_in[15];
    const float* ad2 = (const float*)d_in[16];
    const float* b2  = (const float*)d_in[17];
    float* out = (float*)d_out;

    int E = in_sizes[1] / 2;
    int Etot = E + NN;

    __half* hp;   cudaGetSymbolAddress((void**)&hp, g_hp);
    __half* actA; cudaGetSymbolAddress((void**)&actA, g_actA);
    __half* actB; cudaGetSymbolAddress((void**)&actB, g_actB);
    int* degp;    cudaGetSymbolAddress((void**)&degp, g_deg);
    __half *w0h, *w0l, *w1h, *w1l;
    cudaGetSymbolAddress((void**)&w0h, g_W0h);
    cudaGetSymbolAddress((void**)&w0l, g_W0l);
    cudaGetSymbolAddress((void**)&w1h, g_W1h);
    cudaGetSymbolAddress((void**)&w1l, g_W1l);

    int gemm_grid = (NN + 127) / 128;
    int wpn_grid = (NN + 7) / 8;

    // ---- fork: CSR build + W1 split on s2; W0 split + GEMM0 on main stream
    cudaEventRecord(g_hx.fork, 0);
    cudaStreamWaitEvent(g_hx.s2, g_hx.fork, 0);

    k_splitW<<<64, 256, 0, g_hx.s2>>>(W1, w1h, w1l);
    cudaMemsetAsync(degp, 0, NN * sizeof(int), g_hx.s2);
    k_probe<<<1, 32, 0, g_hx.s2>>>((const int*)ei);
    k_hist<<<(Etot + 255) / 256, 256, 0, g_hx.s2>>>(ei, E, Etot);
    k_scan_a<<<NBLK, 1024, 0, g_hx.s2>>>();
    k_scan_c<<<(NN + 255) / 256, 256, 0, g_hx.s2>>>();
    k_scatter<<<(Etot + 255) / 256, 256, 0, g_hx.s2>>>(ei, E, Etot);
    cudaEventRecord(g_hx.join, g_hx.s2);

    k_splitW<<<64, 256>>>(W0, w0h, w0l);
    k_gemm128<false><<<gemm_grid, 256>>>(x, w0h, w0l, as0, ad0, hp, NN);

    cudaStreamWaitEvent(0, g_hx.join, 0);

    // ---- layer 0 aggregate ----
    k_aggregate128<<<wpn_grid, 256>>>(b0, g0, be0, actA, NN);

    // ---- layer 1 ----
    k_gemm128<true><<<gemm_grid, 256>>>(actA, w1h, w1l, as1, ad1, hp, NN);
    k_aggregate128<<<wpn_grid, 256>>>(b1, g1, be1, actB, NN);

    // ---- layer 2 ----
    k_layer2_gemm_dots<<<wpn_grid, 256>>>(actB, W2, as2, ad2, NN);
    k_aggregate10<<<wpn_grid, 256>>>(b2, out, NN);
}

// round 16
// speedup vs baseline: 1.1422x; 1.0178x over previous
#include <cuda_runtime.h>
#include <cuda_bf16.h>
#include <cuda_fp16.h>
#include <stdint.h>
#include <math.h>

typedef unsigned int u32;

#define NN 50000
#define EMAX 600000
#define ETOT_MAX (EMAX + NN)
#define NBLK ((NN + 1023) / 1024)   // 49

// ---------------- scratch (device globals; no allocations allowed) ----------
__device__ __half g_hp[(size_t)NN * 128];    // fp16 messages
__device__ __half g_actA[(size_t)NN * 128];  // fp16 activations (layer 0 out)
__device__ float g_hp2[NN * 10];
__device__ float g_as[NN * 4];
__device__ float g_ad[NN * 4];
__device__ float g_as2[NN];
__device__ float g_ad2[NN];
__device__ int   g_deg[NN];
__device__ int   g_off[NN + 1];
__device__ int   g_cur[NN];
__device__ int   g_csr[ETOT_MAX];
__device__ int   g_bsum[NBLK];
__device__ int   g_is64;
// pre-split weights (fp16 hi/lo), 128x128 each
__device__ __half g_W0h[16384], g_W0l[16384];
__device__ __half g_W1h[16384], g_W1l[16384];

// host-side stream/event resources, created once at program init.
struct HxStreams {
    cudaStream_t s2;
    cudaEvent_t fork, join;
    HxStreams() {
        cudaStreamCreateWithFlags(&s2, cudaStreamNonBlocking);
        cudaEventCreateWithFlags(&fork, cudaEventDisableTiming);
        cudaEventCreateWithFlags(&join, cudaEventDisableTiming);
    }
};
static HxStreams g_hx;

// ---------------- W pre-split: fp32 -> fp16 hi + fp16 lo ---------------------
__global__ void k_splitW(const float* __restrict__ W,
                         __half* __restrict__ Wh, __half* __restrict__ Wl) {
    int i = blockIdx.x * blockDim.x + threadIdx.x;
    if (i >= 16384) return;
    float v = W[i];
    __half h = __float2half_rn(v);
    Wh[i] = h;
    Wl[i] = __float2half_rn(v - __half2float(h));
}

// ---------------- edge-index dtype probe --------------------------------------
__global__ void k_probe(const int* __restrict__ ei32) {
    if (threadIdx.x == 0) {
        int ok = 1;
        for (int e = 0; e < 64; e++)
            if (ei32[2 * e + 1] != 0) { ok = 0; break; }
        g_is64 = ok;
    }
}

__device__ __forceinline__ int load_idx(const void* ei, long long pos) {
    if (g_is64) return (int)((const long long*)ei)[pos];
    return ((const int*)ei)[pos];
}

// ---------------- CSR build --------------------------------------------------
__global__ void k_hist(const void* __restrict__ ei, int E, int Etot) {
    int e = blockIdx.x * blockDim.x + threadIdx.x;
    if (e >= Etot) return;
    int d = (e < E) ? load_idx(ei, (long long)E + e) : (e - E);
    atomicAdd(&g_deg[d], 1);
}

__global__ void k_scan_a() {
    __shared__ int sh[1024];
    int b = blockIdx.x, t = threadIdx.x;
    int i = b * 1024 + t;
    int v = (i < NN) ? g_deg[i] : 0;
    sh[t] = v;
    __syncthreads();
    for (int off = 1; off < 1024; off <<= 1) {
        int u = (t >= off) ? sh[t - off] : 0;
        __syncthreads();
        sh[t] += u;
        __syncthreads();
    }
    if (i < NN) g_off[i] = sh[t] - v;
    if (t == 1023) g_bsum[b] = sh[t];
}

__global__ void k_scan_c() {
    __shared__ int pre[NBLK];
    if (threadIdx.x == 0) {
        int run = 0;
        for (int b = 0; b < NBLK; b++) { pre[b] = run; run += g_bsum[b]; }
        if (blockIdx.x == 0) g_off[NN] = run;
    }
    __syncthreads();
    int i = blockIdx.x * blockDim.x + threadIdx.x;
    if (i >= NN) return;
    int o = g_off[i] + pre[i >> 10];
    g_off[i] = o;
    g_cur[i] = o;
}

__global__ void k_scatter(const void* __restrict__ ei, int E, int Etot) {
    int e = blockIdx.x * blockDim.x + threadIdx.x;
    if (e >= Etot) return;
    int s, d;
    if (e < E) {
        s = load_idx(ei, e);
        d = load_idx(ei, (long long)E + e);
    } else {
        s = d = e - E;
    }
    int pos = atomicAdd(&g_cur[d], 1);
    g_csr[pos] = s;
}

// ---------------- tensor-core GEMM helpers -----------------------------------
__device__ __forceinline__ u32 s2u(const void* p) {
    return (u32)__cvta_generic_to_shared(p);
}
__device__ __forceinline__ void ldsm4(u32& r0, u32& r1, u32& r2, u32& r3, u32 addr) {
    asm volatile("ldmatrix.sync.aligned.m8n8.x4.shared.b16 {%0,%1,%2,%3}, [%4];"
                 : "=r"(r0), "=r"(r1), "=r"(r2), "=r"(r3) : "r"(addr));
}
__device__ __forceinline__ void ldsm4t(u32& r0, u32& r1, u32& r2, u32& r3, u32 addr) {
    asm volatile("ldmatrix.sync.aligned.m8n8.x4.trans.shared.b16 {%0,%1,%2,%3}, [%4];"
                 : "=r"(r0), "=r"(r1), "=r"(r2), "=r"(r3) : "r"(addr));
}
__device__ __forceinline__ void mma16816h(float* c, const u32* a, u32 b0, u32 b1) {
    asm volatile(
        "mma.sync.aligned.m16n8k16.row.col.f32.f16.f16.f32 "
        "{%0,%1,%2,%3}, {%4,%5,%6,%7}, {%8,%9}, {%0,%1,%2,%3};"
        : "+f"(c[0]), "+f"(c[1]), "+f"(c[2]), "+f"(c[3])
        : "r"(a[0]), "r"(a[1]), "r"(a[2]), "r"(a[3]), "r"(b0), "r"(b1));
}

// C(fp16)[n,128] = A[n,128] @ W[128,128], fp16 mma with W split (hi+lo), fp32 acc.
#define APAD 40
#define WPAD 136
template <bool HALF_A>
__global__ void __launch_bounds__(256, 2)
k_gemm128(const void* __restrict__ A,
          const __half* __restrict__ Wh_g, const __half* __restrict__ Wl_g,
          const float* __restrict__ att_s, const float* __restrict__ att_d,
          __half* __restrict__ C, int n) {
    __shared__ __align__(16) __half As[128][APAD];
    __shared__ __align__(16) __half Wh[32][WPAD];
    __shared__ __align__(16) __half Wl[32][WPAD];

    int tid = threadIdx.x;
    int lane = tid & 31;
    int wid = tid >> 5;
    int warp_m = wid >> 1;
    int warp_n = wid & 1;
    int row0 = blockIdx.x * 128;
    int wrow0 = warp_m * 32;
    int wcol0 = warp_n * 64;

    int a_r = tid >> 3;
    int a_c = (tid & 7) * 4;
    int w_k = tid >> 3;
    int w_cbase = (tid & 7) * 4;

    float acc[2][8][4];
#pragma unroll
    for (int i = 0; i < 2; i++)
#pragma unroll
        for (int j = 0; j < 8; j++)
#pragma unroll
            for (int q = 0; q < 4; q++) acc[i][j][q] = 0.f;

    float4 pa[4];
    uint2 paw[4], pwh[4], pwl[4];
#pragma unroll
    for (int it = 0; it < 4; it++) {
        int grow = row0 + a_r + it * 32;
        if (HALF_A) {
            paw[it] = make_uint2(0u, 0u);
            if (grow < n) paw[it] = *(const uint2*)((const __half*)A + (size_t)grow * 128 + a_c);
        } else {
            pa[it] = make_float4(0.f, 0.f, 0.f, 0.f);
            if (grow < n) pa[it] = *(const float4*)((const float*)A + (size_t)grow * 128 + a_c);
        }
        pwh[it] = *(const uint2*)(Wh_g + (size_t)w_k * 128 + w_cbase + it * 32);
        pwl[it] = *(const uint2*)(Wl_g + (size_t)w_k * 128 + w_cbase + it * 32);
    }

    for (int k0 = 0; k0 < 128; k0 += 32) {
#pragma unroll
        for (int it = 0; it < 4; it++) {
            int r = a_r + it * 32;
            if (HALF_A) {
                *(uint2*)&As[r][a_c] = paw[it];
            } else {
                __half2 h01 = __floats2half2_rn(pa[it].x, pa[it].y);
                __half2 h23 = __floats2half2_rn(pa[it].z, pa[it].w);
                *(__half2*)&As[r][a_c] = h01;
                *(__half2*)&As[r][a_c + 2] = h23;
            }
            int c = w_cbase + it * 32;
            *(uint2*)&Wh[w_k][c] = pwh[it];
            *(uint2*)&Wl[w_k][c] = pwl[it];
        }
        __syncthreads();

        if (k0 + 32 < 128) {
#pragma unroll
            for (int it = 0; it < 4; it++) {
                int grow = row0 + a_r + it * 32;
                if (HALF_A) {
                    paw[it] = make_uint2(0u, 0u);
                    if (grow < n)
                        paw[it] = *(const uint2*)((const __half*)A + (size_t)grow * 128 + k0 + 32 + a_c);
                } else {
                    pa[it] = make_float4(0.f, 0.f, 0.f, 0.f);
                    if (grow < n)
                        pa[it] = *(const float4*)((const float*)A + (size_t)grow * 128 + k0 + 32 + a_c);
                }
                pwh[it] = *(const uint2*)(Wh_g + (size_t)(k0 + 32 + w_k) * 128 + w_cbase + it * 32);
                pwl[it] = *(const uint2*)(Wl_g + (size_t)(k0 + 32 + w_k) * 128 + w_cbase + it * 32);
            }
        }

#pragma unroll
        for (int ks = 0; ks < 32; ks += 16) {
            u32 aa[2][4], bb[4][4];
            int arow = (lane & 15);
            int acol = ks + ((lane >> 4) << 3);
#pragma unroll
            for (int mt = 0; mt < 2; mt++)
                ldsm4(aa[mt][0], aa[mt][1], aa[mt][2], aa[mt][3],
                      s2u(&As[wrow0 + mt * 16 + arow][acol]));
#pragma unroll
            for (int p = 0; p < 4; p++) {
                int j = p * 2 + (lane >> 4);
                ldsm4t(bb[p][0], bb[p][1], bb[p][2], bb[p][3],
                       s2u(&Wh[ks + (lane & 15)][wcol0 + j * 8]));
            }
#pragma unroll
            for (int mt = 0; mt < 2; mt++)
#pragma unroll
                for (int j = 0; j < 8; j++)
                    mma16816h(acc[mt][j], aa[mt], bb[j >> 1][(j & 1) * 2], bb[j >> 1][(j & 1) * 2 + 1]);
#pragma unroll
            for (int p = 0; p < 4; p++) {
                int j = p * 2 + (lane >> 4);
                ldsm4t(bb[p][0], bb[p][1], bb[p][2], bb[p][3],
                       s2u(&Wl[ks + (lane & 15)][wcol0 + j * 8]));
            }
#pragma unroll
            for (int mt = 0; mt < 2; mt++)
#pragma unroll
                for (int j = 0; j < 8; j++)
                    mma16816h(acc[mt][j], aa[mt], bb[j >> 1][(j & 1) * 2], bb[j >> 1][(j & 1) * 2 + 1]);
        }
        __syncthreads();
    }

    float2 vs[8], vd[8];
#pragma unroll
    for (int j = 0; j < 8; j++) {
        int col = wcol0 + j * 8 + (lane & 3) * 2;
        vs[j] = *(const float2*)(att_s + col);
        vd[j] = *(const float2*)(att_d + col);
    }

#pragma unroll
    for (int mt = 0; mt < 2; mt++) {
        int r0 = row0 + wrow0 + mt * 16 + (lane >> 2);
        int r1 = r0 + 8;
        float ps0[2] = {0.f, 0.f}, ps1[2] = {0.f, 0.f};
        float pd0[2] = {0.f, 0.f}, pd1[2] = {0.f, 0.f};
#pragma unroll
        for (int j = 0; j < 8; j++) {
            int cofs = wcol0 + j * 8 + (lane & 3) * 2;
            if (r0 < n)
                *(__half2*)(C + (size_t)r0 * 128 + cofs) =
                    __floats2half2_rn(acc[mt][j][0], acc[mt][j][1]);
            if (r1 < n)
                *(__half2*)(C + (size_t)r1 * 128 + cofs) =
                    __floats2half2_rn(acc[mt][j][2], acc[mt][j][3]);
            int h = j >> 2;
            ps0[h] += acc[mt][j][0] * vs[j].x + acc[mt][j][1] * vs[j].y;
            ps1[h] += acc[mt][j][2] * vs[j].x + acc[mt][j][3] * vs[j].y;
            pd0[h] += acc[mt][j][0] * vd[j].x + acc[mt][j][1] * vd[j].y;
            pd1[h] += acc[mt][j][2] * vd[j].x + acc[mt][j][3] * vd[j].y;
        }
#pragma unroll
        for (int o = 1; o <= 2; o <<= 1) {
#pragma unroll
            for (int h = 0; h < 2; h++) {
                ps0[h] += __shfl_xor_sync(0xffffffffu, ps0[h], o);
                ps1[h] += __shfl_xor_sync(0xffffffffu, ps1[h], o);
                pd0[h] += __shfl_xor_sync(0xffffffffu, pd0[h], o);
                pd1[h] += __shfl_xor_sync(0xffffffffu, pd1[h], o);
            }
        }
        if ((lane & 3) == 0) {
#pragma unroll
            for (int h = 0; h < 2; h++) {
                int hd = warp_n * 2 + h;
                if (r0 < n) { g_as[r0 * 4 + hd] = ps0[h]; g_ad[r0 * 4 + hd] = pd0[h]; }
                if (r1 < n) { g_as[r1 * 4 + hd] = ps1[h]; g_ad[r1 * 4 + hd] = pd1[h]; }
            }
        }
    }
}

__device__ __forceinline__ float leaky(float x) { return x > 0.f ? x : 0.2f * x; }

// ---------------- single-pass segment softmax + aggregate + bias/BN/ELU ------
// LAYER2_FUSE: fold the [128 -> 10] layer-2 GEMM + attn dots into the epilogue
// (warp holds the full post-ELU activation; no actB round trip, one fewer kernel).
#define CHUNK 64
template <bool LAYER2_FUSE>
__global__ void k_aggregate128(const float* __restrict__ bias, const float* __restrict__ gamma,
                               const float* __restrict__ beta, __half* __restrict__ out,
                               const float* __restrict__ W2, const float* __restrict__ as2,
                               const float* __restrict__ ad2, int n) {
    __shared__ float4 s_wv[8][CHUNK];
    __shared__ int    s_idx[8][CHUNK];
    __shared__ float  W2t[10 * 128];
    __shared__ float  s_as2[10], s_ad2[10];

    if (LAYER2_FUSE) {
        int t = threadIdx.x;
        for (int i = t; i < 1280; i += 256) {
            int k = i / 10, c = i % 10;
            W2t[c * 128 + k] = W2[i];
        }
        if (t < 10) { s_as2[t] = as2[t]; s_ad2[t] = ad2[t]; }
        __syncthreads();
    }

    int gt = blockIdx.x * blockDim.x + threadIdx.x;
    int node = gt >> 5;
    if (node >= n) return;
    int lane = threadIdx.x & 31;
    int wrp = (threadIdx.x >> 5);
    int s0 = g_off[node], s1 = g_off[node + 1];

    float ad0 = g_ad[node * 4 + 0], ad1 = g_ad[node * 4 + 1];
    float ad2v = g_ad[node * 4 + 2], ad3 = g_ad[node * 4 + 3];

    int hl = lane >> 3;
    float dl0 = 0.f, dl1 = 0.f, dl2 = 0.f, dl3 = 0.f;
    float ax = 0.f, ay = 0.f, az = 0.f, aw = 0.f;

    for (int c0 = s0; c0 < s1; c0 += CHUNK) {
        int cnt = min(CHUNK, s1 - c0);
        for (int i = lane; i < cnt; i += 32) {
            int s = g_csr[c0 + i];
            float4 av = *(const float4*)(g_as + s * 4);
            float4 wv;
            wv.x = __expf(leaky(av.x + ad0));
            wv.y = __expf(leaky(av.y + ad1));
            wv.z = __expf(leaky(av.z + ad2v));
            wv.w = __expf(leaky(av.w + ad3));
            dl0 += wv.x; dl1 += wv.y; dl2 += wv.z; dl3 += wv.w;
            s_wv[wrp][i] = wv;
            s_idx[wrp][i] = s;
        }
        __syncwarp();
#pragma unroll 4
        for (int j = 0; j < cnt; j++) {
            int s = s_idx[wrp][j];
            float wt = ((const float*)&s_wv[wrp][j])[hl];
            const __half2* p = (const __half2*)(g_hp + (size_t)s * 128 + lane * 4);
            float2 v01 = __half22float2(p[0]);
            float2 v23 = __half22float2(p[1]);
            ax += v01.x * wt; ay += v01.y * wt; az += v23.x * wt; aw += v23.y * wt;
        }
        __syncwarp();
    }

#pragma unroll
    for (int o = 16; o > 0; o >>= 1) {
        dl0 += __shfl_xor_sync(0xffffffffu, dl0, o);
        dl1 += __shfl_xor_sync(0xffffffffu, dl1, o);
        dl2 += __shfl_xor_sync(0xffffffffu, dl2, o);
        dl3 += __shfl_xor_sync(0xffffffffu, dl3, o);
    }
    float dh = (hl == 0) ? dl0 : (hl == 1) ? dl1 : (hl == 2) ? dl2 : dl3;
    float inv = 1.f / (dh + 1e-16f);

    const float invsq = rsqrtf(1.0f + 1e-5f);
    float res[4] = {ax * inv, ay * inv, az * inv, aw * inv};
#pragma unroll
    for (int j = 0; j < 4; j++) {
        int c = lane * 4 + j;
        float v = res[j] + bias[c];
        v = v * (gamma[c] * invsq) + beta[c];
        res[j] = (v > 0.f) ? v : expm1f(v);
    }

    if (LAYER2_FUSE) {
        // layer-2 GEMM + attn dots, directly from registers
        float as_acc = 0.f, ad_acc = 0.f;
#pragma unroll
        for (int c = 0; c < 10; c++) {
            const float* wc = W2t + c * 128 + lane * 4;
            float p = res[0] * wc[0] + res[1] * wc[1] + res[2] * wc[2] + res[3] * wc[3];
#pragma unroll
            for (int o = 16; o > 0; o >>= 1) p += __shfl_xor_sync(0xffffffffu, p, o);
            if (lane == 0) g_hp2[node * 10 + c] = p;
            as_acc += p * s_as2[c];
            ad_acc += p * s_ad2[c];
        }
        if (lane == 0) { g_as2[node] = as_acc; g_ad2[node] = ad_acc; }
    } else {
        __half2* po = (__half2*)(out + (size_t)node * 128 + lane * 4);
        po[0] = __floats2half2_rn(res[0], res[1]);
        po[1] = __floats2half2_rn(res[2], res[3]);
    }
}

// single-pass edge-parallel aggregate for CLS layer
__global__ void k_aggregate10(const float* __restrict__ b2, float* __restrict__ out, int n) {
    int gt = blockIdx.x * blockDim.x + threadIdx.x;
    int node = gt >> 5;
    if (node >= n) return;
    int lane = threadIdx.x & 31;
    int s0 = g_off[node], s1 = g_off[node + 1];
    float adn = g_ad2[node];

    float dsum = 0.f;
    float acc[10];
#pragma unroll
    for (int c = 0; c < 10; c++) acc[c] = 0.f;
    for (int i = s0 + lane; i < s1; i += 32) {
        int s = g_csr[i];
        float w = __expf(leaky(g_as2[s] + adn));
        dsum += w;
        const float2* p = (const float2*)(g_hp2 + s * 10);
#pragma unroll
        for (int c = 0; c < 5; c++) {
            float2 v = p[c];
            acc[2 * c]     += v.x * w;
            acc[2 * c + 1] += v.y * w;
        }
    }
#pragma unroll
    for (int o = 16; o > 0; o >>= 1) {
        dsum += __shfl_xor_sync(0xffffffffu, dsum, o);
#pragma unroll
        for (int c = 0; c < 10; c++)
            acc[c] += __shfl_xor_sync(0xffffffffu, acc[c], o);
    }
    float inv = 1.f / (dsum + 1e-16f);
    if (lane < 10) out[node * 10 + lane] = acc[lane] * inv + b2[lane];
}

// ---------------- launch -----------------------------------------------------
extern "C" void kernel_launch(void* const* d_in, const int* in_sizes, int n_in,
                              void* d_out, int out_size) {
    const float* x   = (const float*)d_in[0];
    const void*  ei  = d_in[1];
    const float* W0  = (const float*)d_in[2];
    const float* as0 = (const float*)d_in[3];
    const float* ad0 = (const float*)d_in[4];
    const float* b0  = (const float*)d_in[5];
    const float* g0  = (const float*)d_in[6];
    const float* be0 = (const float*)d_in[7];
    const float* W1  = (const float*)d_in[8];
    const float* as1 = (const float*)d_in[9];
    const float* ad1 = (const float*)d_in[10];
    const float* b1  = (const float*)d_in[11];
    const float* g1  = (const float*)d_in[12];
    const float* be1 = (const float*)d_in[13];
    const float* W2  = (const float*)d_in[14];
    const float* as2 = (const float*)d_in[15];
    const float* ad2 = (const float*)d_in[16];
    const float* b2  = (const float*)d_in[17];
    float* out = (float*)d_out;

    int E = in_sizes[1] / 2;
    int Etot = E + NN;

    __half* hp;   cudaGetSymbolAddress((void**)&hp, g_hp);
    __half* actA; cudaGetSymbolAddress((void**)&actA, g_actA);
    int* degp;    cudaGetSymbolAddress((void**)&degp, g_deg);
    __half *w0h, *w0l, *w1h, *w1l;
    cudaGetSymbolAddress((void**)&w0h, g_W0h);
    cudaGetSymbolAddress((void**)&w0l, g_W0l);
    cudaGetSymbolAddress((void**)&w1h, g_W1h);
    cudaGetSymbolAddress((void**)&w1l, g_W1l);

    int gemm_grid = (NN + 127) / 128;
    int wpn_grid = (NN + 7) / 8;

    // ---- fork: CSR build + W1 split on s2; W0 split + GEMM0 on main stream
    cudaEventRecord(g_hx.fork, 0);
    cudaStreamWaitEvent(g_hx.s2, g_hx.fork, 0);

    k_splitW<<<64, 256, 0, g_hx.s2>>>(W1, w1h, w1l);
    cudaMemsetAsync(degp, 0, NN * sizeof(int), g_hx.s2);
    k_probe<<<1, 32, 0, g_hx.s2>>>((const int*)ei);
    k_hist<<<(Etot + 255) / 256, 256, 0, g_hx.s2>>>(ei, E, Etot);
    k_scan_a<<<NBLK, 1024, 0, g_hx.s2>>>();
    k_scan_c<<<(NN + 255) / 256, 256, 0, g_hx.s2>>>();
    k_scatter<<<(Etot + 255) / 256, 256, 0, g_hx.s2>>>(ei, E, Etot);
    cudaEventRecord(g_hx.join, g_hx.s2);

    k_splitW<<<64, 256>>>(W0, w0h, w0l);
    k_gemm128<false><<<gemm_grid, 256>>>(x, w0h, w0l, as0, ad0, hp, NN);

    cudaStreamWaitEvent(0, g_hx.join, 0);

    // ---- layer 0 aggregate (writes fp16 actA) ----
    k_aggregate128<false><<<wpn_grid, 256>>>(b0, g0, be0, actA, nullptr, nullptr, nullptr, NN);

    // ---- layer 1 GEMM + aggregate fused with layer-2 projection ----
    k_gemm128<true><<<gemm_grid, 256>>>(actA, w1h, w1l, as1, ad1, hp, NN);
    k_aggregate128<true><<<wpn_grid, 256>>>(b1, g1, be1, nullptr, W2, as2, ad2, NN);

    // ---- layer 2 aggregate ----
    k_aggregate10<<<wpn_grid, 256>>>(b2, out, NN);
}

// round 17
// speedup vs baseline: 1.1958x; 1.0469x over previous
#include <cuda_runtime.h>
#include <cuda_bf16.h>
#include <cuda_fp16.h>
#include <stdint.h>
#include <math.h>

typedef unsigned int u32;

#define NN 50000
#define EMAX 600000
#define ETOT_MAX (EMAX + NN)
#define NBLK ((NN + 1023) / 1024)   // 49

// ---------------- scratch (device globals; no allocations allowed) ----------
__device__ __half g_hp[(size_t)NN * 128];    // fp16 messages
__device__ __half g_actA[(size_t)NN * 128];  // fp16 activations (layer 0 out)
__device__ float g_hp2[NN * 10];
__device__ float g_as[NN * 4];
__device__ float g_ad[NN * 4];
__device__ float g_as2[NN];
__device__ float g_ad2[NN];
__device__ int   g_deg[NN];
__device__ int   g_off[NN + 1];
__device__ int   g_cur[NN];
__device__ int   g_csr[ETOT_MAX];
__device__ int   g_bsum[NBLK];
__device__ int   g_is64;
// pre-split weights (fp16 hi/lo), 128x128 each
__device__ __half g_W0h[16384], g_W0l[16384];
__device__ __half g_W1h[16384], g_W1l[16384];

// host-side stream/event resources, created once at program init.
struct HxStreams {
    cudaStream_t s2;
    cudaEvent_t fork, join;
    HxStreams() {
        cudaStreamCreateWithFlags(&s2, cudaStreamNonBlocking);
        cudaEventCreateWithFlags(&fork, cudaEventDisableTiming);
        cudaEventCreateWithFlags(&join, cudaEventDisableTiming);
    }
};
static HxStreams g_hx;

// ---------------- W pre-split: fp32 -> fp16 hi + fp16 lo ---------------------
__global__ void k_splitW(const float* __restrict__ W,
                         __half* __restrict__ Wh, __half* __restrict__ Wl) {
    int i = blockIdx.x * blockDim.x + threadIdx.x;
    if (i >= 16384) return;
    float v = W[i];
    __half h = __float2half_rn(v);
    Wh[i] = h;
    Wl[i] = __float2half_rn(v - __half2float(h));
}

// ---------------- edge-index dtype probe --------------------------------------
__global__ void k_probe(const int* __restrict__ ei32) {
    if (threadIdx.x == 0) {
        int ok = 1;
        for (int e = 0; e < 64; e++)
            if (ei32[2 * e + 1] != 0) { ok = 0; break; }
        g_is64 = ok;
    }
}

__device__ __forceinline__ int load_idx(const void* ei, long long pos) {
    if (g_is64) return (int)((const long long*)ei)[pos];
    return ((const int*)ei)[pos];
}

// ---------------- CSR build --------------------------------------------------
__global__ void k_hist(const void* __restrict__ ei, int E, int Etot) {
    int e = blockIdx.x * blockDim.x + threadIdx.x;
    if (e >= Etot) return;
    int d = (e < E) ? load_idx(ei, (long long)E + e) : (e - E);
    atomicAdd(&g_deg[d], 1);
}

__global__ void k_scan_a() {
    __shared__ int sh[1024];
    int b = blockIdx.x, t = threadIdx.x;
    int i = b * 1024 + t;
    int v = (i < NN) ? g_deg[i] : 0;
    sh[t] = v;
    __syncthreads();
    for (int off = 1; off < 1024; off <<= 1) {
        int u = (t >= off) ? sh[t - off] : 0;
        __syncthreads();
        sh[t] += u;
        __syncthreads();
    }
    if (i < NN) g_off[i] = sh[t] - v;
    if (t == 1023) g_bsum[b] = sh[t];
}

__global__ void k_scan_c() {
    __shared__ int pre[NBLK];
    if (threadIdx.x == 0) {
        int run = 0;
        for (int b = 0; b < NBLK; b++) { pre[b] = run; run += g_bsum[b]; }
        if (blockIdx.x == 0) g_off[NN] = run;
    }
    __syncthreads();
    int i = blockIdx.x * blockDim.x + threadIdx.x;
    if (i >= NN) return;
    int o = g_off[i] + pre[i >> 10];
    g_off[i] = o;
    g_cur[i] = o;
}

__global__ void k_scatter(const void* __restrict__ ei, int E, int Etot) {
    int e = blockIdx.x * blockDim.x + threadIdx.x;
    if (e >= Etot) return;
    int s, d;
    if (e < E) {
        s = load_idx(ei, e);
        d = load_idx(ei, (long long)E + e);
    } else {
        s = d = e - E;
    }
    int pos = atomicAdd(&g_cur[d], 1);
    g_csr[pos] = s;
}

// ---------------- tensor-core GEMM helpers -----------------------------------
__device__ __forceinline__ u32 s2u(const void* p) {
    return (u32)__cvta_generic_to_shared(p);
}
__device__ __forceinline__ void ldsm4(u32& r0, u32& r1, u32& r2, u32& r3, u32 addr) {
    asm volatile("ldmatrix.sync.aligned.m8n8.x4.shared.b16 {%0,%1,%2,%3}, [%4];"
                 : "=r"(r0), "=r"(r1), "=r"(r2), "=r"(r3) : "r"(addr));
}
__device__ __forceinline__ void ldsm4t(u32& r0, u32& r1, u32& r2, u32& r3, u32 addr) {
    asm volatile("ldmatrix.sync.aligned.m8n8.x4.trans.shared.b16 {%0,%1,%2,%3}, [%4];"
                 : "=r"(r0), "=r"(r1), "=r"(r2), "=r"(r3) : "r"(addr));
}
__device__ __forceinline__ void mma16816h(float* c, const u32* a, u32 b0, u32 b1) {
    asm volatile(
        "mma.sync.aligned.m16n8k16.row.col.f32.f16.f16.f32 "
        "{%0,%1,%2,%3}, {%4,%5,%6,%7}, {%8,%9}, {%0,%1,%2,%3};"
        : "+f"(c[0]), "+f"(c[1]), "+f"(c[2]), "+f"(c[3])
        : "r"(a[0]), "r"(a[1]), "r"(a[2]), "r"(a[3]), "r"(b0), "r"(b1));
}

// C(fp16)[n,128] = A[n,128] @ W[128,128], fp16 mma with W split (hi+lo), fp32 acc.
#define APAD 40
#define WPAD 136
template <bool HALF_A>
__global__ void __launch_bounds__(256, 2)
k_gemm128(const void* __restrict__ A,
          const __half* __restrict__ Wh_g, const __half* __restrict__ Wl_g,
          const float* __restrict__ att_s, const float* __restrict__ att_d,
          __half* __restrict__ C, int n) {
    __shared__ __align__(16) __half As[128][APAD];
    __shared__ __align__(16) __half Wh[32][WPAD];
    __shared__ __align__(16) __half Wl[32][WPAD];

    int tid = threadIdx.x;
    int lane = tid & 31;
    int wid = tid >> 5;
    int warp_m = wid >> 1;
    int warp_n = wid & 1;
    int row0 = blockIdx.x * 128;
    int wrow0 = warp_m * 32;
    int wcol0 = warp_n * 64;

    int a_r = tid >> 3;
    int a_c = (tid & 7) * 4;
    int w_k = tid >> 3;
    int w_cbase = (tid & 7) * 4;

    float acc[2][8][4];
#pragma unroll
    for (int i = 0; i < 2; i++)
#pragma unroll
        for (int j = 0; j < 8; j++)
#pragma unroll
            for (int q = 0; q < 4; q++) acc[i][j][q] = 0.f;

    float4 pa[4];
    uint2 paw[4], pwh[4], pwl[4];
#pragma unroll
    for (int it = 0; it < 4; it++) {
        int grow = row0 + a_r + it * 32;
        if (HALF_A) {
            paw[it] = make_uint2(0u, 0u);
            if (grow < n) paw[it] = *(const uint2*)((const __half*)A + (size_t)grow * 128 + a_c);
        } else {
            pa[it] = make_float4(0.f, 0.f, 0.f, 0.f);
            if (grow < n) pa[it] = *(const float4*)((const float*)A + (size_t)grow * 128 + a_c);
        }
        pwh[it] = *(const uint2*)(Wh_g + (size_t)w_k * 128 + w_cbase + it * 32);
        pwl[it] = *(const uint2*)(Wl_g + (size_t)w_k * 128 + w_cbase + it * 32);
    }

    for (int k0 = 0; k0 < 128; k0 += 32) {
#pragma unroll
        for (int it = 0; it < 4; it++) {
            int r = a_r + it * 32;
            if (HALF_A) {
                *(uint2*)&As[r][a_c] = paw[it];
            } else {
                __half2 h01 = __floats2half2_rn(pa[it].x, pa[it].y);
                __half2 h23 = __floats2half2_rn(pa[it].z, pa[it].w);
                *(__half2*)&As[r][a_c] = h01;
                *(__half2*)&As[r][a_c + 2] = h23;
            }
            int c = w_cbase + it * 32;
            *(uint2*)&Wh[w_k][c] = pwh[it];
            *(uint2*)&Wl[w_k][c] = pwl[it];
        }
        __syncthreads();

        if (k0 + 32 < 128) {
#pragma unroll
            for (int it = 0; it < 4; it++) {
                int grow = row0 + a_r + it * 32;
                if (HALF_A) {
                    paw[it] = make_uint2(0u, 0u);
                    if (grow < n)
                        paw[it] = *(const uint2*)((const __half*)A + (size_t)grow * 128 + k0 + 32 + a_c);
                } else {
                    pa[it] = make_float4(0.f, 0.f, 0.f, 0.f);
                    if (grow < n)
                        pa[it] = *(const float4*)((const float*)A + (size_t)grow * 128 + k0 + 32 + a_c);
                }
                pwh[it] = *(const uint2*)(Wh_g + (size_t)(k0 + 32 + w_k) * 128 + w_cbase + it * 32);
                pwl[it] = *(const uint2*)(Wl_g + (size_t)(k0 + 32 + w_k) * 128 + w_cbase + it * 32);
            }
        }

#pragma unroll
        for (int ks = 0; ks < 32; ks += 16) {
            u32 aa[2][4], bb[4][4];
            int arow = (lane & 15);
            int acol = ks + ((lane >> 4) << 3);
#pragma unroll
            for (int mt = 0; mt < 2; mt++)
                ldsm4(aa[mt][0], aa[mt][1], aa[mt][2], aa[mt][3],
                      s2u(&As[wrow0 + mt * 16 + arow][acol]));
#pragma unroll
            for (int p = 0; p < 4; p++) {
                int j = p * 2 + (lane >> 4);
                ldsm4t(bb[p][0], bb[p][1], bb[p][2], bb[p][3],
                       s2u(&Wh[ks + (lane & 15)][wcol0 + j * 8]));
            }
#pragma unroll
            for (int mt = 0; mt < 2; mt++)
#pragma unroll
                for (int j = 0; j < 8; j++)
                    mma16816h(acc[mt][j], aa[mt], bb[j >> 1][(j & 1) * 2], bb[j >> 1][(j & 1) * 2 + 1]);
#pragma unroll
            for (int p = 0; p < 4; p++) {
                int j = p * 2 + (lane >> 4);
                ldsm4t(bb[p][0], bb[p][1], bb[p][2], bb[p][3],
                       s2u(&Wl[ks + (lane & 15)][wcol0 + j * 8]));
            }
#pragma unroll
            for (int mt = 0; mt < 2; mt++)
#pragma unroll
                for (int j = 0; j < 8; j++)
                    mma16816h(acc[mt][j], aa[mt], bb[j >> 1][(j & 1) * 2], bb[j >> 1][(j & 1) * 2 + 1]);
        }
        __syncthreads();
    }

    float2 vs[8], vd[8];
#pragma unroll
    for (int j = 0; j < 8; j++) {
        int col = wcol0 + j * 8 + (lane & 3) * 2;
        vs[j] = *(const float2*)(att_s + col);
        vd[j] = *(const float2*)(att_d + col);
    }

#pragma unroll
    for (int mt = 0; mt < 2; mt++) {
        int r0 = row0 + wrow0 + mt * 16 + (lane >> 2);
        int r1 = r0 + 8;
        float ps0[2] = {0.f, 0.f}, ps1[2] = {0.f, 0.f};
        float pd0[2] = {0.f, 0.f}, pd1[2] = {0.f, 0.f};
#pragma unroll
        for (int j = 0; j < 8; j++) {
            int cofs = wcol0 + j * 8 + (lane & 3) * 2;
            if (r0 < n)
                *(__half2*)(C + (size_t)r0 * 128 + cofs) =
                    __floats2half2_rn(acc[mt][j][0], acc[mt][j][1]);
            if (r1 < n)
                *(__half2*)(C + (size_t)r1 * 128 + cofs) =
                    __floats2half2_rn(acc[mt][j][2], acc[mt][j][3]);
            int h = j >> 2;
            ps0[h] += acc[mt][j][0] * vs[j].x + acc[mt][j][1] * vs[j].y;
            ps1[h] += acc[mt][j][2] * vs[j].x + acc[mt][j][3] * vs[j].y;
            pd0[h] += acc[mt][j][0] * vd[j].x + acc[mt][j][1] * vd[j].y;
            pd1[h] += acc[mt][j][2] * vd[j].x + acc[mt][j][3] * vd[j].y;
        }
#pragma unroll
        for (int o = 1; o <= 2; o <<= 1) {
#pragma unroll
            for (int h = 0; h < 2; h++) {
                ps0[h] += __shfl_xor_sync(0xffffffffu, ps0[h], o);
                ps1[h] += __shfl_xor_sync(0xffffffffu, ps1[h], o);
                pd0[h] += __shfl_xor_sync(0xffffffffu, pd0[h], o);
                pd1[h] += __shfl_xor_sync(0xffffffffu, pd1[h], o);
            }
        }
        if ((lane & 3) == 0) {
#pragma unroll
            for (int h = 0; h < 2; h++) {
                int hd = warp_n * 2 + h;
                if (r0 < n) { g_as[r0 * 4 + hd] = ps0[h]; g_ad[r0 * 4 + hd] = pd0[h]; }
                if (r1 < n) { g_as[r1 * 4 + hd] = ps1[h]; g_ad[r1 * 4 + hd] = pd1[h]; }
            }
        }
    }
}

__device__ __forceinline__ float leaky(float x) { return x > 0.f ? x : 0.2f * x; }

// FMA-pipe exp: exp(x) = 2^(x*log2e); deg-5 poly on f in [-0.5,0.5], rel err ~2e-6.
__device__ __forceinline__ float fexp(float x) {
    float t = x * 1.4426950408889634f;
    int i = __float2int_rn(t);
    float f = t - (float)i;
    float p = 1.3333558e-3f;
    p = fmaf(p, f, 9.6181291e-3f);
    p = fmaf(p, f, 5.5504109e-2f);
    p = fmaf(p, f, 2.4022651e-1f);
    p = fmaf(p, f, 6.9314718e-1f);
    p = fmaf(p, f, 1.0f);
    return __int_as_float(__float_as_int(p) + (i << 23));
}

// ---------------- single-pass segment softmax + aggregate + bias/BN/ELU ------
// Hybrid exp: heads 0/1 on MUFU (__expf), heads 2/3 on FMA pipe (fexp).
#define CHUNK 64
template <bool LAYER2_FUSE>
__global__ void k_aggregate128(const float* __restrict__ bias, const float* __restrict__ gamma,
                               const float* __restrict__ beta, __half* __restrict__ out,
                               const float* __restrict__ W2, const float* __restrict__ as2,
                               const float* __restrict__ ad2, int n) {
    __shared__ float4 s_wv[8][CHUNK];
    __shared__ int    s_idx[8][CHUNK];
    __shared__ float  W2t[10 * 128];
    __shared__ float  s_as2[10], s_ad2[10];

    if (LAYER2_FUSE) {
        int t = threadIdx.x;
        for (int i = t; i < 1280; i += 256) {
            int k = i / 10, c = i % 10;
            W2t[c * 128 + k] = W2[i];
        }
        if (t < 10) { s_as2[t] = as2[t]; s_ad2[t] = ad2[t]; }
        __syncthreads();
    }

    int gt = blockIdx.x * blockDim.x + threadIdx.x;
    int node = gt >> 5;
    if (node >= n) return;
    int lane = threadIdx.x & 31;
    int wrp = (threadIdx.x >> 5);
    int s0 = g_off[node], s1 = g_off[node + 1];

    float ad0 = g_ad[node * 4 + 0], ad1 = g_ad[node * 4 + 1];
    float ad2v = g_ad[node * 4 + 2], ad3 = g_ad[node * 4 + 3];

    int hl = lane >> 3;
    float dl0 = 0.f, dl1 = 0.f, dl2 = 0.f, dl3 = 0.f;
    float ax = 0.f, ay = 0.f, az = 0.f, aw = 0.f;

    for (int c0 = s0; c0 < s1; c0 += CHUNK) {
        int cnt = min(CHUNK, s1 - c0);
        for (int i = lane; i < cnt; i += 32) {
            int s = g_csr[c0 + i];
            float4 av = *(const float4*)(g_as + s * 4);
            float4 wv;
            wv.x = __expf(leaky(av.x + ad0));   // MUFU
            wv.y = __expf(leaky(av.y + ad1));   // MUFU
            wv.z = fexp(leaky(av.z + ad2v));    // FMA pipe
            wv.w = fexp(leaky(av.w + ad3));     // FMA pipe
            dl0 += wv.x; dl1 += wv.y; dl2 += wv.z; dl3 += wv.w;
            s_wv[wrp][i] = wv;
            s_idx[wrp][i] = s;
        }
        __syncwarp();
#pragma unroll 4
        for (int j = 0; j < cnt; j++) {
            int s = s_idx[wrp][j];
            float wt = ((const float*)&s_wv[wrp][j])[hl];
            uint2 raw = *(const uint2*)(g_hp + (size_t)s * 128 + lane * 4);  // one LDG.64
            float2 v01 = __half22float2(*reinterpret_cast<__half2*>(&raw.x));
            float2 v23 = __half22float2(*reinterpret_cast<__half2*>(&raw.y));
            ax += v01.x * wt; ay += v01.y * wt; az += v23.x * wt; aw += v23.y * wt;
        }
        __syncwarp();
    }

#pragma unroll
    for (int o = 16; o > 0; o >>= 1) {
        dl0 += __shfl_xor_sync(0xffffffffu, dl0, o);
        dl1 += __shfl_xor_sync(0xffffffffu, dl1, o);
        dl2 += __shfl_xor_sync(0xffffffffu, dl2, o);
        dl3 += __shfl_xor_sync(0xffffffffu, dl3, o);
    }
    float dh = (hl == 0) ? dl0 : (hl == 1) ? dl1 : (hl == 2) ? dl2 : dl3;
    float inv = 1.f / (dh + 1e-16f);

    const float invsq = rsqrtf(1.0f + 1e-5f);
    float res[4] = {ax * inv, ay * inv, az * inv, aw * inv};
#pragma unroll
    for (int j = 0; j < 4; j++) {
        int c = lane * 4 + j;
        float v = res[j] + bias[c];
        v = v * (gamma[c] * invsq) + beta[c];
        res[j] = (v > 0.f) ? v : expm1f(v);
    }

    if (LAYER2_FUSE) {
        float as_acc = 0.f, ad_acc = 0.f;
#pragma unroll
        for (int c = 0; c < 10; c++) {
            const float* wc = W2t + c * 128 + lane * 4;
            float p = res[0] * wc[0] + res[1] * wc[1] + res[2] * wc[2] + res[3] * wc[3];
#pragma unroll
            for (int o = 16; o > 0; o >>= 1) p += __shfl_xor_sync(0xffffffffu, p, o);
            if (lane == 0) g_hp2[node * 10 + c] = p;
            as_acc += p * s_as2[c];
            ad_acc += p * s_ad2[c];
        }
        if (lane == 0) { g_as2[node] = as_acc; g_ad2[node] = ad_acc; }
    } else {
        __half2* po = (__half2*)(out + (size_t)node * 128 + lane * 4);
        po[0] = __floats2half2_rn(res[0], res[1]);
        po[1] = __floats2half2_rn(res[2], res[3]);
    }
}

// single-pass edge-parallel aggregate for CLS layer
__global__ void k_aggregate10(const float* __restrict__ b2, float* __restrict__ out, int n) {
    int gt = blockIdx.x * blockDim.x + threadIdx.x;
    int node = gt >> 5;
    if (node >= n) return;
    int lane = threadIdx.x & 31;
    int s0 = g_off[node], s1 = g_off[node + 1];
    float adn = g_ad2[node];

    float dsum = 0.f;
    float acc[10];
#pragma unroll
    for (int c = 0; c < 10; c++) acc[c] = 0.f;
    for (int i = s0 + lane; i < s1; i += 32) {
        int s = g_csr[i];
        float w = fexp(leaky(g_as2[s] + adn));
        dsum += w;
        const float2* p = (const float2*)(g_hp2 + s * 10);
#pragma unroll
        for (int c = 0; c < 5; c++) {
            float2 v = p[c];
            acc[2 * c]     += v.x * w;
            acc[2 * c + 1] += v.y * w;
        }
    }
#pragma unroll
    for (int o = 16; o > 0; o >>= 1) {
        dsum += __shfl_xor_sync(0xffffffffu, dsum, o);
#pragma unroll
        for (int c = 0; c < 10; c++)
            acc[c] += __shfl_xor_sync(0xffffffffu, acc[c], o);
    }
    float inv = 1.f / (dsum + 1e-16f);
    if (lane < 10) out[node * 10 + lane] = acc[lane] * inv + b2[lane];
}

// ---------------- launch -----------------------------------------------------
extern "C" void kernel_launch(void* const* d_in, const int* in_sizes, int n_in,
                              void* d_out, int out_size) {
    const float* x   = (const float*)d_in[0];
    const void*  ei  = d_in[1];
    const float* W0  = (const float*)d_in[2];
    const float* as0 = (const float*)d_in[3];
    const float* ad0 = (const float*)d_in[4];
    const float* b0  = (const float*)d_in[5];
    const float* g0  = (const float*)d_in[6];
    const float* be0 = (const float*)d_in[7];
    const float* W1  = (const float*)d_in[8];
    const float* as1 = (const float*)d_in[9];
    const float* ad1 = (const float*)d_in[10];
    const float* b1  = (const float*)d_in[11];
    const float* g1  = (const float*)d_in[12];
    const float* be1 = (const float*)d_in[13];
    const float* W2  = (const float*)d_in[14];
    const float* as2 = (const float*)d_in[15];
    const float* ad2 = (const float*)d_in[16];
    const float* b2  = (const float*)d_in[17];
    float* out = (float*)d_out;

    int E = in_sizes[1] / 2;
    int Etot = E + NN;

    __half* hp;   cudaGetSymbolAddress((void**)&hp, g_hp);
    __half* actA; cudaGetSymbolAddress((void**)&actA, g_actA);
    int* degp;    cudaGetSymbolAddress((void**)&degp, g_deg);
    __half *w0h, *w0l, *w1h, *w1l;
    cudaGetSymbolAddress((void**)&w0h, g_W0h);
    cudaGetSymbolAddress((void**)&w0l, g_W0l);
    cudaGetSymbolAddress((void**)&w1h, g_W1h);
    cudaGetSymbolAddress((void**)&w1l, g_W1l);

    int gemm_grid = (NN + 127) / 128;
    int wpn_grid = (NN + 7) / 8;

    // ---- fork: CSR build + W1 split on s2; W0 split + GEMM0 on main stream
    cudaEventRecord(g_hx.fork, 0);
    cudaStreamWaitEvent(g_hx.s2, g_hx.fork, 0);

    k_splitW<<<64, 256, 0, g_hx.s2>>>(W1, w1h, w1l);
    cudaMemsetAsync(degp, 0, NN * sizeof(int), g_hx.s2);
    k_probe<<<1, 32, 0, g_hx.s2>>>((const int*)ei);
    k_hist<<<(Etot + 255) / 256, 256, 0, g_hx.s2>>>(ei, E, Etot);
    k_scan_a<<<NBLK, 1024, 0, g_hx.s2>>>();
    k_scan_c<<<(NN + 255) / 256, 256, 0, g_hx.s2>>>();
    k_scatter<<<(Etot + 255) / 256, 256, 0, g_hx.s2>>>(ei, E, Etot);
    cudaEventRecord(g_hx.join, g_hx.s2);

    k_splitW<<<64, 256>>>(W0, w0h, w0l);
    k_gemm128<false><<<gemm_grid, 256>>>(x, w0h, w0l, as0, ad0, hp, NN);

    cudaStreamWaitEvent(0, g_hx.join, 0);

    // ---- layer 0 aggregate (writes fp16 actA) ----
    k_aggregate128<false><<<wpn_grid, 256>>>(b0, g0, be0, actA, nullptr, nullptr, nullptr, NN);

    // ---- layer 1 GEMM + aggregate fused with layer-2 projection ----
    k_gemm128<true><<<gemm_grid, 256>>>(actA, w1h, w1l, as1, ad1, hp, NN);
    k_aggregate128<true><<<wpn_grid, 256>>>(b1, g1, be1, nullptr, W2, as2, ad2, NN);

    // ---- layer 2 aggregate ----
    k_aggregate10<<<wpn_grid, 256>>>(b2, out, NN);
}